// round 1
// baseline (speedup 1.0000x reference)
#include <cuda_runtime.h>

#define H 256
#define NMAX 204800
#define BMAX 4096

// Scratch (device globals: no allocations allowed)
__device__ float g_e[NMAX];
__device__ float g_rst[BMAX * H];
__device__ int   g_off[BMAX + 1];

// ---------------------------------------------------------------------------
// Prefix scan of ragged lengths. Detects int32 vs int64 storage at runtime:
// int32 interpretation sums to exactly n only if data really is int32.
// ---------------------------------------------------------------------------
__global__ __launch_bounds__(1024) void scan_kernel(const void* lens_raw, int b, int n_total) {
    __shared__ long long s[1024];
    __shared__ int use64;
    const int tid = threadIdx.x;
    const int* p32 = (const int*)lens_raw;

    // 1) decide dtype: sum int32 interpretation
    long long local = 0;
    for (int i = tid; i < b; i += 1024) local += (long long)p32[i];
    s[tid] = local;
    __syncthreads();
    for (int o = 512; o > 0; o >>= 1) {
        if (tid < o) s[tid] += s[tid + o];
        __syncthreads();
    }
    if (tid == 0) use64 = (s[0] == (long long)n_total) ? 0 : 1;
    __syncthreads();
    const int u64 = use64;
    __syncthreads();

    // 2) each thread owns 4 consecutive segments
    const int PER = 4;  // b <= 4096
    long long v[PER];
    long long loc = 0;
    #pragma unroll
    for (int q = 0; q < PER; q++) {
        int i = tid * PER + q;
        long long val = 0;
        if (i < b) val = u64 ? ((const long long*)lens_raw)[i] : (long long)p32[i];
        v[q] = val;
        loc += val;
    }
    s[tid] = loc;
    __syncthreads();
    // inclusive Hillis-Steele scan over thread sums
    for (int o = 1; o < 1024; o <<= 1) {
        long long t = (tid >= o) ? s[tid - o] : 0;
        __syncthreads();
        s[tid] += t;
        __syncthreads();
    }
    long long run = s[tid] - loc;  // exclusive prefix of this thread's chunk
    #pragma unroll
    for (int q = 0; q < PER; q++) {
        int i = tid * PER + q;
        if (i < b) {
            g_off[i] = (int)run;
            run += v[q];
            if (i == b - 1) g_off[b] = (int)run;
        }
    }
}

// ---------------------------------------------------------------------------
// Fused e-GEMM: h = [feats|ctx] @ [Wu.T;Wv.T] (K=512), then
// e[i] = sum_j sigmoid(h[i][j] + bu[j]) * We[j].  h never hits memory.
// Tile: 64 rows x 256 cols, BK=16, 256 threads, per-thread 4x16 fp32.
// ---------------------------------------------------------------------------
__global__ __launch_bounds__(256, 2) void e_gemm_kernel(
    const float* __restrict__ feats, const float* __restrict__ ctx,
    const float* __restrict__ Wu, const float* __restrict__ Wv,
    const float* __restrict__ bu, const float* __restrict__ We, int n)
{
    const int BM = 64, BK = 16;
    __shared__ float As[BK][BM];     // A transposed
    __shared__ float Bs[BK][H];
    __shared__ float sbu[H], sWe[H];

    const int tid = threadIdx.x;
    const int tx = tid & 15;          // col group: cols [tx*16, tx*16+16)
    const int ty = tid >> 4;          // row group: rows [ty*4, ty*4+4)
    const int row0 = blockIdx.x * BM;

    sbu[tid] = bu[tid];
    sWe[tid] = We[tid];

    float acc[4][16];
    #pragma unroll
    for (int r = 0; r < 4; r++)
        #pragma unroll
        for (int c = 0; c < 16; c++) acc[r][c] = 0.f;

    const int lrow = tid >> 2;        // A load: row 0..63
    const int lq   = tid & 3;         // A load: float4 index 0..3

    for (int k0 = 0; k0 < 2 * H; k0 += BK) {
        const float* Ap; const float* Wp; int kk0;
        if (k0 < H) { Ap = feats; Wp = Wu; kk0 = k0; }
        else        { Ap = ctx;   Wp = Wv; kk0 = k0 - H; }

        int arow = row0 + lrow;
        if (arow >= n) arow = n - 1;
        float4 av = *(const float4*)(Ap + (size_t)arow * H + kk0 + lq * 4);
        // B[k][j] = W[j][kk0+k]; thread tid loads row j=tid of W (coalesced)
        float4 bv0 = *(const float4*)(Wp + (size_t)tid * H + kk0 + 0);
        float4 bv1 = *(const float4*)(Wp + (size_t)tid * H + kk0 + 4);
        float4 bv2 = *(const float4*)(Wp + (size_t)tid * H + kk0 + 8);
        float4 bv3 = *(const float4*)(Wp + (size_t)tid * H + kk0 + 12);

        __syncthreads();   // previous compute done before overwrite
        As[lq * 4 + 0][lrow] = av.x;
        As[lq * 4 + 1][lrow] = av.y;
        As[lq * 4 + 2][lrow] = av.z;
        As[lq * 4 + 3][lrow] = av.w;
        Bs[ 0][tid] = bv0.x; Bs[ 1][tid] = bv0.y; Bs[ 2][tid] = bv0.z; Bs[ 3][tid] = bv0.w;
        Bs[ 4][tid] = bv1.x; Bs[ 5][tid] = bv1.y; Bs[ 6][tid] = bv1.z; Bs[ 7][tid] = bv1.w;
        Bs[ 8][tid] = bv2.x; Bs[ 9][tid] = bv2.y; Bs[10][tid] = bv2.z; Bs[11][tid] = bv2.w;
        Bs[12][tid] = bv3.x; Bs[13][tid] = bv3.y; Bs[14][tid] = bv3.z; Bs[15][tid] = bv3.w;
        __syncthreads();

        #pragma unroll
        for (int kk = 0; kk < BK; kk++) {
            float4 a = *(const float4*)&As[kk][ty * 4];
            float bb[16];
            *(float4*)&bb[0]  = *(const float4*)&Bs[kk][tx * 16 + 0];
            *(float4*)&bb[4]  = *(const float4*)&Bs[kk][tx * 16 + 4];
            *(float4*)&bb[8]  = *(const float4*)&Bs[kk][tx * 16 + 8];
            *(float4*)&bb[12] = *(const float4*)&Bs[kk][tx * 16 + 12];
            #pragma unroll
            for (int c = 0; c < 16; c++) {
                acc[0][c] += a.x * bb[c];
                acc[1][c] += a.y * bb[c];
                acc[2][c] += a.z * bb[c];
                acc[3][c] += a.w * bb[c];
            }
        }
    }

    // Epilogue: sigmoid + dot with We, reduce across the 16 col-group lanes.
    float part[4] = {0.f, 0.f, 0.f, 0.f};
    #pragma unroll
    for (int c = 0; c < 16; c++) {
        const int col = tx * 16 + c;
        const float buc = sbu[col];
        const float wec = sWe[col];
        #pragma unroll
        for (int r = 0; r < 4; r++) {
            float x = acc[r][c] + buc;
            float sg = 1.f / (1.f + __expf(-x));
            part[r] += sg * wec;
        }
    }
    #pragma unroll
    for (int o = 8; o > 0; o >>= 1) {
        #pragma unroll
        for (int r = 0; r < 4; r++)
            part[r] += __shfl_xor_sync(0xffffffffu, part[r], o);
    }
    if (tx == 0) {
        #pragma unroll
        for (int r = 0; r < 4; r++) {
            int row = row0 + ty * 4 + r;
            if (row < n) g_e[row] = part[r];
        }
    }
}

// ---------------------------------------------------------------------------
// Segment softmax + weighted pooling. One block per segment.
// ---------------------------------------------------------------------------
__global__ __launch_bounds__(256) void pool_kernel(const float* __restrict__ feats, int b) {
    __shared__ float red[256];
    __shared__ float sex[256];
    const int seg = blockIdx.x;
    const int tid = threadIdx.x;
    const int base = g_off[seg];
    const int len  = g_off[seg + 1] - base;

    if (len <= 0) { g_rst[(size_t)seg * H + tid] = 0.f; return; }

    // segment max
    float m = -1e30f;
    for (int i = tid; i < len; i += 256) m = fmaxf(m, g_e[base + i]);
    red[tid] = m;
    __syncthreads();
    for (int o = 128; o > 0; o >>= 1) {
        if (tid < o) red[tid] = fmaxf(red[tid], red[tid + o]);
        __syncthreads();
    }
    m = red[0];
    __syncthreads();

    // denominator
    float d = 0.f;
    for (int i = tid; i < len; i += 256) d += __expf(g_e[base + i] - m);
    red[tid] = d;
    __syncthreads();
    for (int o = 128; o > 0; o >>= 1) {
        if (tid < o) red[tid] += red[tid + o];
        __syncthreads();
    }
    const float inv = 1.f / red[0];
    __syncthreads();

    // weighted sum: thread tid owns output column tid
    float acc = 0.f;
    for (int s = 0; s < len; s += 256) {
        int c = len - s; if (c > 256) c = 256;
        sex[tid] = (tid < c) ? __expf(g_e[base + s + tid] - m) : 0.f;
        __syncthreads();
        #pragma unroll 4
        for (int i = 0; i < c; i++)
            acc += sex[i] * feats[(size_t)(base + s + i) * H + tid];
        __syncthreads();
    }
    g_rst[(size_t)seg * H + tid] = acc * inv;
}

// ---------------------------------------------------------------------------
// out = rst @ Wout.T  (M=4096, K=256). Same tiling as the e-GEMM.
// ---------------------------------------------------------------------------
__global__ __launch_bounds__(256, 2) void out_gemm_kernel(
    float* __restrict__ out, const float* __restrict__ Wout, int m)
{
    const int BM = 64, BK = 16;
    __shared__ float As[BK][BM];
    __shared__ float Bs[BK][H];

    const int tid = threadIdx.x;
    const int tx = tid & 15;
    const int ty = tid >> 4;
    const int row0 = blockIdx.x * BM;

    float acc[4][16];
    #pragma unroll
    for (int r = 0; r < 4; r++)
        #pragma unroll
        for (int c = 0; c < 16; c++) acc[r][c] = 0.f;

    const int lrow = tid >> 2;
    const int lq   = tid & 3;

    for (int k0 = 0; k0 < H; k0 += BK) {
        int arow = row0 + lrow;
        if (arow >= m) arow = m - 1;
        float4 av = *(const float4*)(g_rst + (size_t)arow * H + k0 + lq * 4);
        float4 bv0 = *(const float4*)(Wout + (size_t)tid * H + k0 + 0);
        float4 bv1 = *(const float4*)(Wout + (size_t)tid * H + k0 + 4);
        float4 bv2 = *(const float4*)(Wout + (size_t)tid * H + k0 + 8);
        float4 bv3 = *(const float4*)(Wout + (size_t)tid * H + k0 + 12);

        __syncthreads();
        As[lq * 4 + 0][lrow] = av.x;
        As[lq * 4 + 1][lrow] = av.y;
        As[lq * 4 + 2][lrow] = av.z;
        As[lq * 4 + 3][lrow] = av.w;
        Bs[ 0][tid] = bv0.x; Bs[ 1][tid] = bv0.y; Bs[ 2][tid] = bv0.z; Bs[ 3][tid] = bv0.w;
        Bs[ 4][tid] = bv1.x; Bs[ 5][tid] = bv1.y; Bs[ 6][tid] = bv1.z; Bs[ 7][tid] = bv1.w;
        Bs[ 8][tid] = bv2.x; Bs[ 9][tid] = bv2.y; Bs[10][tid] = bv2.z; Bs[11][tid] = bv2.w;
        Bs[12][tid] = bv3.x; Bs[13][tid] = bv3.y; Bs[14][tid] = bv3.z; Bs[15][tid] = bv3.w;
        __syncthreads();

        #pragma unroll
        for (int kk = 0; kk < BK; kk++) {
            float4 a = *(const float4*)&As[kk][ty * 4];
            float bb[16];
            *(float4*)&bb[0]  = *(const float4*)&Bs[kk][tx * 16 + 0];
            *(float4*)&bb[4]  = *(const float4*)&Bs[kk][tx * 16 + 4];
            *(float4*)&bb[8]  = *(const float4*)&Bs[kk][tx * 16 + 8];
            *(float4*)&bb[12] = *(const float4*)&Bs[kk][tx * 16 + 12];
            #pragma unroll
            for (int c = 0; c < 16; c++) {
                acc[0][c] += a.x * bb[c];
                acc[1][c] += a.y * bb[c];
                acc[2][c] += a.z * bb[c];
                acc[3][c] += a.w * bb[c];
            }
        }
    }

    #pragma unroll
    for (int r = 0; r < 4; r++) {
        int row = row0 + ty * 4 + r;
        if (row < m) {
            #pragma unroll
            for (int cq = 0; cq < 4; cq++) {
                float4 v;
                v.x = acc[r][cq * 4 + 0];
                v.y = acc[r][cq * 4 + 1];
                v.z = acc[r][cq * 4 + 2];
                v.w = acc[r][cq * 4 + 3];
                *(float4*)(out + (size_t)row * H + tx * 16 + cq * 4) = v;
            }
        }
    }
}

extern "C" void kernel_launch(void* const* d_in, const int* in_sizes, int n_in,
                              void* d_out, int out_size) {
    const float* feats = (const float*)d_in[0];
    const float* ctx   = (const float*)d_in[1];
    const void*  lens  = d_in[2];
    const float* Wu    = (const float*)d_in[3];
    const float* bu    = (const float*)d_in[4];
    const float* Wv    = (const float*)d_in[5];
    const float* We    = (const float*)d_in[6];
    const float* Wout  = (const float*)d_in[7];
    float* out = (float*)d_out;

    const int n = in_sizes[0] / H;       // 204800
    const int b = out_size / H;          // 4096 (robust to lens dtype)

    scan_kernel<<<1, 1024>>>(lens, b, n);
    e_gemm_kernel<<<(n + 63) / 64, 256>>>(feats, ctx, Wu, Wv, bu, We, n);
    pool_kernel<<<b, 256>>>(feats, b);
    out_gemm_kernel<<<(b + 63) / 64, 256>>>(out, Wout, b);
}

// round 3
// speedup vs baseline: 3.2877x; 3.2877x over previous
#include <cuda_runtime.h>
#include <cstdint>

#define H 256
#define NMAX 204800
#define BMAX 4096

__device__ float g_e[NMAX];
__device__ float g_rst[BMAX * H];
__device__ int   g_off[BMAX + 1];

// ---------------------------------------------------------------------------
// Prefix scan of ragged lengths (runtime int32/int64 detection).
// ---------------------------------------------------------------------------
__global__ __launch_bounds__(1024) void scan_kernel(const void* lens_raw, int b, int n_total) {
    __shared__ long long s[1024];
    __shared__ int use64;
    const int tid = threadIdx.x;
    const int* p32 = (const int*)lens_raw;

    long long local = 0;
    for (int i = tid; i < b; i += 1024) local += (long long)p32[i];
    s[tid] = local;
    __syncthreads();
    for (int o = 512; o > 0; o >>= 1) {
        if (tid < o) s[tid] += s[tid + o];
        __syncthreads();
    }
    if (tid == 0) use64 = (s[0] == (long long)n_total) ? 0 : 1;
    __syncthreads();
    const int u64 = use64;
    __syncthreads();

    const int PER = 4;
    long long v[PER];
    long long loc = 0;
    #pragma unroll
    for (int q = 0; q < PER; q++) {
        int i = tid * PER + q;
        long long val = 0;
        if (i < b) val = u64 ? ((const long long*)lens_raw)[i] : (long long)p32[i];
        v[q] = val;
        loc += val;
    }
    s[tid] = loc;
    __syncthreads();
    for (int o = 1; o < 1024; o <<= 1) {
        long long t = (tid >= o) ? s[tid - o] : 0;
        __syncthreads();
        s[tid] += t;
        __syncthreads();
    }
    long long run = s[tid] - loc;
    #pragma unroll
    for (int q = 0; q < PER; q++) {
        int i = tid * PER + q;
        if (i < b) {
            g_off[i] = (int)run;
            run += v[q];
            if (i == b - 1) g_off[b] = (int)run;
        }
    }
}

// ---------------------------------------------------------------------------
// tf32 MMA helpers
// ---------------------------------------------------------------------------
__device__ __forceinline__ uint32_t f2tf32(float x) {
    uint32_t r;
    asm("cvt.rna.tf32.f32 %0, %1;\n" : "=r"(r) : "f"(x));
    return r;
}
__device__ __forceinline__ void mma_tf32(float& d0, float& d1, float& d2, float& d3,
                                         uint32_t a0, uint32_t a1, uint32_t a2, uint32_t a3,
                                         uint32_t b0, uint32_t b1) {
    asm volatile("mma.sync.aligned.m16n8k8.row.col.f32.tf32.tf32.f32 "
                 "{%0,%1,%2,%3},{%4,%5,%6,%7},{%8,%9},{%0,%1,%2,%3};\n"
                 : "+f"(d0), "+f"(d1), "+f"(d2), "+f"(d3)
                 : "r"(a0), "r"(a1), "r"(a2), "r"(a3), "r"(b0), "r"(b1));
}

#define APITCH 36
#define BPITCH 264   // 264 % 32 == 8 -> B-frag banks (8k+g)%32 all distinct

// ---------------------------------------------------------------------------
// Fused e-GEMM, tf32 tensor cores. BM=64, BN=256 (full), K=512, BK=32.
// 8 warps in 2x4; warp tile 32x64 = 2 m-tiles x 8 n-tiles of m16n8k8.
// Epilogue: e[i] = sum_j sigmoid(h+bu)*We fully in-block.
// ---------------------------------------------------------------------------
__global__ __launch_bounds__(256, 2) void e_gemm_mma(
    const float* __restrict__ feats, const float* __restrict__ ctx,
    const float* __restrict__ Wu, const float* __restrict__ Wv,
    const float* __restrict__ bu, const float* __restrict__ We, int n)
{
    __shared__ float As[64 * APITCH];
    __shared__ float Bs[32 * BPITCH];
    __shared__ float sbu[H], sWe[H];
    __shared__ float ered[64][4];

    const int tid  = threadIdx.x;
    const int lane = tid & 31;
    const int warp = tid >> 5;
    const int wm = warp >> 2;          // 0..1
    const int wn = warp & 3;           // 0..3
    const int g = lane >> 2;           // 0..7
    const int t4 = lane & 3;           // 0..3
    const int row0 = blockIdx.x * 64;

    sbu[tid] = bu[tid];
    sWe[tid] = We[tid];

    float acc[2][8][4];
    #pragma unroll
    for (int mi = 0; mi < 2; mi++)
        #pragma unroll
        for (int ni = 0; ni < 8; ni++)
            #pragma unroll
            for (int q = 0; q < 4; q++) acc[mi][ni][q] = 0.f;

    // A loader: 512 float4, thread handles idx = tid, tid+256
    // B loader: thread loads 32 floats of W row j=tid
    for (int k0 = 0; k0 < 2 * H; k0 += 32) {
        const float* Ap; const float* Wp;
        const int kk0 = k0 & (H - 1);
        if (k0 < H) { Ap = feats; Wp = Wu; }
        else        { Ap = ctx;   Wp = Wv; }

        float4 av[2];
        #pragma unroll
        for (int i = 0; i < 2; i++) {
            int idx = tid + i * 256;
            int ar = idx >> 3, ac4 = idx & 7;
            int grow = row0 + ar; if (grow >= n) grow = n - 1;
            av[i] = *(const float4*)(Ap + (size_t)grow * H + kk0 + ac4 * 4);
        }
        float4 bv[8];
        #pragma unroll
        for (int i = 0; i < 8; i++)
            bv[i] = *(const float4*)(Wp + (size_t)tid * H + kk0 + i * 4);

        __syncthreads();
        #pragma unroll
        for (int i = 0; i < 2; i++) {
            int idx = tid + i * 256;
            int ar = idx >> 3, ac = (idx & 7) * 4;
            float* p = As + ar * APITCH + ac;
            p[0] = __uint_as_float(f2tf32(av[i].x));
            p[1] = __uint_as_float(f2tf32(av[i].y));
            p[2] = __uint_as_float(f2tf32(av[i].z));
            p[3] = __uint_as_float(f2tf32(av[i].w));
        }
        #pragma unroll
        for (int i = 0; i < 8; i++) {
            Bs[(i * 4 + 0) * BPITCH + tid] = __uint_as_float(f2tf32(bv[i].x));
            Bs[(i * 4 + 1) * BPITCH + tid] = __uint_as_float(f2tf32(bv[i].y));
            Bs[(i * 4 + 2) * BPITCH + tid] = __uint_as_float(f2tf32(bv[i].z));
            Bs[(i * 4 + 3) * BPITCH + tid] = __uint_as_float(f2tf32(bv[i].w));
        }
        __syncthreads();

        #pragma unroll
        for (int ks = 0; ks < 4; ks++) {
            const int kb = ks * 8;
            uint32_t af[2][4];
            #pragma unroll
            for (int mi = 0; mi < 2; mi++) {
                const float* ab = As + (wm * 32 + mi * 16) * APITCH;
                af[mi][0] = __float_as_uint(ab[(g    ) * APITCH + kb + t4    ]);
                af[mi][1] = __float_as_uint(ab[(g + 8) * APITCH + kb + t4    ]);
                af[mi][2] = __float_as_uint(ab[(g    ) * APITCH + kb + t4 + 4]);
                af[mi][3] = __float_as_uint(ab[(g + 8) * APITCH + kb + t4 + 4]);
            }
            uint32_t bf[8][2];
            #pragma unroll
            for (int ni = 0; ni < 8; ni++) {
                const int nc = wn * 64 + ni * 8 + g;
                bf[ni][0] = __float_as_uint(Bs[(kb + t4    ) * BPITCH + nc]);
                bf[ni][1] = __float_as_uint(Bs[(kb + t4 + 4) * BPITCH + nc]);
            }
            #pragma unroll
            for (int mi = 0; mi < 2; mi++)
                #pragma unroll
                for (int ni = 0; ni < 8; ni++)
                    mma_tf32(acc[mi][ni][0], acc[mi][ni][1], acc[mi][ni][2], acc[mi][ni][3],
                             af[mi][0], af[mi][1], af[mi][2], af[mi][3],
                             bf[ni][0], bf[ni][1]);
        }
    }

    // Epilogue: sigmoid(h+bu)·We, row partials
    float part[4] = {0.f, 0.f, 0.f, 0.f};   // rows: wm*32 + mi*16 + {0,8} + g
    #pragma unroll
    for (int mi = 0; mi < 2; mi++) {
        #pragma unroll
        for (int ni = 0; ni < 8; ni++) {
            const int c0 = wn * 64 + ni * 8 + t4 * 2;
            const int c1 = c0 + 1;
            const float w0 = sWe[c0], w1 = sWe[c1];
            const float b0 = sbu[c0], b1 = sbu[c1];
            float x;
            x = acc[mi][ni][0] + b0; part[mi * 2 + 0] += w0 / (1.f + __expf(-x));
            x = acc[mi][ni][1] + b1; part[mi * 2 + 0] += w1 / (1.f + __expf(-x));
            x = acc[mi][ni][2] + b0; part[mi * 2 + 1] += w0 / (1.f + __expf(-x));
            x = acc[mi][ni][3] + b1; part[mi * 2 + 1] += w1 / (1.f + __expf(-x));
        }
    }
    #pragma unroll
    for (int o = 1; o <= 2; o <<= 1)
        #pragma unroll
        for (int p = 0; p < 4; p++)
            part[p] += __shfl_xor_sync(0xffffffffu, part[p], o);
    if (t4 == 0) {
        #pragma unroll
        for (int p = 0; p < 4; p++) {
            int rl = wm * 32 + (p >> 1) * 16 + (p & 1) * 8 + g;
            ered[rl][wn] = part[p];
        }
    }
    __syncthreads();
    if (tid < 64) {
        int row = row0 + tid;
        if (row < n)
            g_e[row] = ered[tid][0] + ered[tid][1] + ered[tid][2] + ered[tid][3];
    }
}

// ---------------------------------------------------------------------------
// Segment softmax + weighted pooling. One block per segment.
// ---------------------------------------------------------------------------
__global__ __launch_bounds__(256) void pool_kernel(const float* __restrict__ feats, int b) {
    __shared__ float red[256];
    __shared__ float sex[256];
    const int seg = blockIdx.x;
    const int tid = threadIdx.x;
    const int base = g_off[seg];
    const int len  = g_off[seg + 1] - base;

    if (len <= 0) { g_rst[(size_t)seg * H + tid] = 0.f; return; }

    float m = -1e30f;
    for (int i = tid; i < len; i += 256) m = fmaxf(m, g_e[base + i]);
    red[tid] = m;
    __syncthreads();
    for (int o = 128; o > 0; o >>= 1) {
        if (tid < o) red[tid] = fmaxf(red[tid], red[tid + o]);
        __syncthreads();
    }
    m = red[0];
    __syncthreads();

    float d = 0.f;
    for (int i = tid; i < len; i += 256) d += __expf(g_e[base + i] - m);
    red[tid] = d;
    __syncthreads();
    for (int o = 128; o > 0; o >>= 1) {
        if (tid < o) red[tid] += red[tid + o];
        __syncthreads();
    }
    const float inv = 1.f / red[0];
    __syncthreads();

    float acc = 0.f;
    for (int s = 0; s < len; s += 256) {
        int c = len - s; if (c > 256) c = 256;
        sex[tid] = (tid < c) ? __expf(g_e[base + s + tid] - m) : 0.f;
        __syncthreads();
        #pragma unroll 4
        for (int i = 0; i < c; i++)
            acc += sex[i] * feats[(size_t)(base + s + i) * H + tid];
        __syncthreads();
    }
    g_rst[(size_t)seg * H + tid] = acc * inv;
}

// ---------------------------------------------------------------------------
// out = rst @ Wout.T via tf32 MMA. BM=32, BN=256, K=256 -> grid = b/32 = 128.
// 8 warps 2x4; warp tile 16x64 = 1 m-tile x 8 n-tiles.
// ---------------------------------------------------------------------------
__global__ __launch_bounds__(256, 2) void out_gemm_mma(
    float* __restrict__ out, const float* __restrict__ Wout, int m)
{
    __shared__ float As[32 * APITCH];
    __shared__ float Bs[32 * BPITCH];

    const int tid  = threadIdx.x;
    const int lane = tid & 31;
    const int warp = tid >> 5;
    const int wm = warp >> 2;
    const int wn = warp & 3;
    const int g = lane >> 2;
    const int t4 = lane & 3;
    const int row0 = blockIdx.x * 32;

    float acc[8][4];
    #pragma unroll
    for (int ni = 0; ni < 8; ni++)
        #pragma unroll
        for (int q = 0; q < 4; q++) acc[ni][q] = 0.f;

    for (int k0 = 0; k0 < H; k0 += 32) {
        // A: 32 rows x 32 k = 256 float4, one per thread
        int ar = tid >> 3, ac4 = tid & 7;
        int grow = row0 + ar; if (grow >= m) grow = m - 1;
        float4 av = *(const float4*)(g_rst + (size_t)grow * H + k0 + ac4 * 4);
        float4 bv[8];
        #pragma unroll
        for (int i = 0; i < 8; i++)
            bv[i] = *(const float4*)(Wout + (size_t)tid * H + k0 + i * 4);

        __syncthreads();
        {
            float* p = As + ar * APITCH + ac4 * 4;
            p[0] = __uint_as_float(f2tf32(av.x));
            p[1] = __uint_as_float(f2tf32(av.y));
            p[2] = __uint_as_float(f2tf32(av.z));
            p[3] = __uint_as_float(f2tf32(av.w));
        }
        #pragma unroll
        for (int i = 0; i < 8; i++) {
            Bs[(i * 4 + 0) * BPITCH + tid] = __uint_as_float(f2tf32(bv[i].x));
            Bs[(i * 4 + 1) * BPITCH + tid] = __uint_as_float(f2tf32(bv[i].y));
            Bs[(i * 4 + 2) * BPITCH + tid] = __uint_as_float(f2tf32(bv[i].z));
            Bs[(i * 4 + 3) * BPITCH + tid] = __uint_as_float(f2tf32(bv[i].w));
        }
        __syncthreads();

        #pragma unroll
        for (int ks = 0; ks < 4; ks++) {
            const int kb = ks * 8;
            const float* ab = As + (wm * 16) * APITCH;
            uint32_t a0 = __float_as_uint(ab[(g    ) * APITCH + kb + t4    ]);
            uint32_t a1 = __float_as_uint(ab[(g + 8) * APITCH + kb + t4    ]);
            uint32_t a2 = __float_as_uint(ab[(g    ) * APITCH + kb + t4 + 4]);
            uint32_t a3 = __float_as_uint(ab[(g + 8) * APITCH + kb + t4 + 4]);
            #pragma unroll
            for (int ni = 0; ni < 8; ni++) {
                const int nc = wn * 64 + ni * 8 + g;
                uint32_t b0 = __float_as_uint(Bs[(kb + t4    ) * BPITCH + nc]);
                uint32_t b1 = __float_as_uint(Bs[(kb + t4 + 4) * BPITCH + nc]);
                mma_tf32(acc[ni][0], acc[ni][1], acc[ni][2], acc[ni][3],
                         a0, a1, a2, a3, b0, b1);
            }
        }
    }

    const int r0 = row0 + wm * 16 + g;
    const int r1 = r0 + 8;
    #pragma unroll
    for (int ni = 0; ni < 8; ni++) {
        const int c0 = wn * 64 + ni * 8 + t4 * 2;
        if (r0 < m) *(float2*)(out + (size_t)r0 * H + c0) = make_float2(acc[ni][0], acc[ni][1]);
        if (r1 < m) *(float2*)(out + (size_t)r1 * H + c0) = make_float2(acc[ni][2], acc[ni][3]);
    }
}

extern "C" void kernel_launch(void* const* d_in, const int* in_sizes, int n_in,
                              void* d_out, int out_size) {
    const float* feats = (const float*)d_in[0];
    const float* ctx   = (const float*)d_in[1];
    const void*  lens  = d_in[2];
    const float* Wu    = (const float*)d_in[3];
    const float* bu    = (const float*)d_in[4];
    const float* Wv    = (const float*)d_in[5];
    const float* We    = (const float*)d_in[6];
    const float* Wout  = (const float*)d_in[7];
    float* out = (float*)d_out;

    const int n = in_sizes[0] / H;
    const int b = out_size / H;

    scan_kernel<<<1, 1024>>>(lens, b, n);
    e_gemm_mma<<<(n + 63) / 64, 256>>>(feats, ctx, Wu, Wv, bu, We, n);
    pool_kernel<<<b, 256>>>(feats, b);
    out_gemm_mma<<<(b + 31) / 32, 256>>>(out, Wout, b);
}

// round 5
// speedup vs baseline: 3.6911x; 1.1227x over previous
#include <cuda_runtime.h>
#include <cstdint>

#define H 256
#define NMAX 204800
#define BMAX 4096

__device__ float g_e[NMAX];
__device__ float g_rst[BMAX * H];
__device__ int   g_off[BMAX + 1];

// ---------------------------------------------------------------------------
// Prefix scan of ragged lengths (runtime int32/int64 detection).
// ---------------------------------------------------------------------------
__global__ __launch_bounds__(1024) void scan_kernel(const void* lens_raw, int b, int n_total) {
    __shared__ long long s[1024];
    __shared__ int use64;
    const int tid = threadIdx.x;
    const int* p32 = (const int*)lens_raw;

    long long local = 0;
    for (int i = tid; i < b; i += 1024) local += (long long)p32[i];
    s[tid] = local;
    __syncthreads();
    for (int o = 512; o > 0; o >>= 1) {
        if (tid < o) s[tid] += s[tid + o];
        __syncthreads();
    }
    if (tid == 0) use64 = (s[0] == (long long)n_total) ? 0 : 1;
    __syncthreads();
    const int u64 = use64;
    __syncthreads();

    const int PER = 4;
    long long v[PER];
    long long loc = 0;
    #pragma unroll
    for (int q = 0; q < PER; q++) {
        int i = tid * PER + q;
        long long val = 0;
        if (i < b) val = u64 ? ((const long long*)lens_raw)[i] : (long long)p32[i];
        v[q] = val;
        loc += val;
    }
    s[tid] = loc;
    __syncthreads();
    for (int o = 1; o < 1024; o <<= 1) {
        long long t = (tid >= o) ? s[tid - o] : 0;
        __syncthreads();
        s[tid] += t;
        __syncthreads();
    }
    long long run = s[tid] - loc;
    #pragma unroll
    for (int q = 0; q < PER; q++) {
        int i = tid * PER + q;
        if (i < b) {
            g_off[i] = (int)run;
            run += v[q];
            if (i == b - 1) g_off[b] = (int)run;
        }
    }
}

// ---------------------------------------------------------------------------
// MMA + cp.async helpers
// ---------------------------------------------------------------------------
__device__ __forceinline__ void mma_tf32(float& d0, float& d1, float& d2, float& d3,
                                         uint32_t a0, uint32_t a1, uint32_t a2, uint32_t a3,
                                         uint32_t b0, uint32_t b1) {
    asm volatile("mma.sync.aligned.m16n8k8.row.col.f32.tf32.tf32.f32 "
                 "{%0,%1,%2,%3},{%4,%5,%6,%7},{%8,%9},{%0,%1,%2,%3};\n"
                 : "+f"(d0), "+f"(d1), "+f"(d2), "+f"(d3)
                 : "r"(a0), "r"(a1), "r"(a2), "r"(a3), "r"(b0), "r"(b1));
}
__device__ __forceinline__ void cpa16(uint32_t dst, const float* src) {
    asm volatile("cp.async.cg.shared.global [%0], [%1], 16;\n" :: "r"(dst), "l"(src));
}
#define CP_COMMIT() asm volatile("cp.async.commit_group;\n" ::: "memory")
#define CP_WAIT1()  asm volatile("cp.async.wait_group 1;\n" ::: "memory")
#define CP_WAIT0()  asm volatile("cp.async.wait_group 0;\n" ::: "memory")

// Pitch 36 floats: 16B-aligned quad slots; fragment bank = (4g + t4) % 32 conflict-free.
#define PITCH 36
#define A_ST  (64 * PITCH)    // e-gemm A stage floats
#define B_ST  (256 * PITCH)   // B stage floats (K-major: [col j][k])

// ---------------------------------------------------------------------------
// Fused e-GEMM, tf32 MMA, cp.async 2-stage pipeline.
// BM=64, BN=256, K=512, BK=32. 8 warps 2x4; warp tile 32x64.
// Raw fp32 fed to HMMA.tf32 (hardware truncation).
// ---------------------------------------------------------------------------
__global__ __launch_bounds__(256, 2) void e_gemm_mma(
    const float* __restrict__ feats, const float* __restrict__ ctx,
    const float* __restrict__ Wu, const float* __restrict__ Wv,
    const float* __restrict__ bu, const float* __restrict__ We, int n)
{
    extern __shared__ float sm[];
    float* As  = sm;                       // [2][A_ST]
    float* Bsm = sm + 2 * A_ST;            // [2][B_ST]
    float* sbu = Bsm + 2 * B_ST;
    float* sWe = sbu + H;
    float* ered = sWe + H;                 // [64][4]

    const int tid  = threadIdx.x;
    const int lane = tid & 31;
    const int warp = tid >> 5;
    const int wm = warp >> 2;
    const int wn = warp & 3;
    const int g  = lane >> 2;
    const int t4 = lane & 3;
    const int row0 = blockIdx.x * 64;

    sbu[tid] = bu[tid];
    sWe[tid] = We[tid];

    const uint32_t sAb = (uint32_t)__cvta_generic_to_shared(As);
    const uint32_t sBb = (uint32_t)__cvta_generic_to_shared(Bsm);

    float acc[2][8][4];
    #pragma unroll
    for (int mi = 0; mi < 2; mi++)
        #pragma unroll
        for (int ni = 0; ni < 8; ni++)
            #pragma unroll
            for (int q = 0; q < 4; q++) acc[mi][ni][q] = 0.f;

    auto issue = [&](int buf, int k0) {
        const float* Ap; const float* Wp;
        const int kk0 = k0 & (H - 1);
        if (k0 < H) { Ap = feats; Wp = Wu; }
        else        { Ap = ctx;   Wp = Wv; }
        #pragma unroll
        for (int q = 0; q < 2; q++) {
            int i = tid + q * 256;
            int ar = i >> 3, kq = i & 7;
            int grow = row0 + ar; if (grow >= n) grow = n - 1;
            cpa16(sAb + (uint32_t)(buf * A_ST + ar * PITCH + kq * 4) * 4u,
                  Ap + (size_t)grow * H + kk0 + kq * 4);
        }
        #pragma unroll
        for (int q = 0; q < 8; q++) {
            cpa16(sBb + (uint32_t)(buf * B_ST + tid * PITCH + q * 4) * 4u,
                  Wp + (size_t)tid * H + kk0 + q * 4);
        }
        CP_COMMIT();
    };

    issue(0, 0);
    for (int s = 0; s < 16; s++) {
        if (s + 1 < 16) { issue((s + 1) & 1, (s + 1) * 32); CP_WAIT1(); }
        else            { CP_WAIT0(); }
        __syncthreads();

        const float* Ab = As  + (s & 1) * A_ST;
        const float* Bb = Bsm + (s & 1) * B_ST;

        #pragma unroll
        for (int ks = 0; ks < 4; ks++) {
            const int kb = ks * 8;
            uint32_t af[2][4];
            #pragma unroll
            for (int mi = 0; mi < 2; mi++) {
                const float* ab = Ab + (wm * 32 + mi * 16) * PITCH;
                af[mi][0] = __float_as_uint(ab[(g    ) * PITCH + kb + t4    ]);
                af[mi][1] = __float_as_uint(ab[(g + 8) * PITCH + kb + t4    ]);
                af[mi][2] = __float_as_uint(ab[(g    ) * PITCH + kb + t4 + 4]);
                af[mi][3] = __float_as_uint(ab[(g + 8) * PITCH + kb + t4 + 4]);
            }
            uint32_t bf[8][2];
            #pragma unroll
            for (int ni = 0; ni < 8; ni++) {
                const int nc = wn * 64 + ni * 8 + g;
                bf[ni][0] = __float_as_uint(Bb[nc * PITCH + kb + t4    ]);
                bf[ni][1] = __float_as_uint(Bb[nc * PITCH + kb + t4 + 4]);
            }
            #pragma unroll
            for (int mi = 0; mi < 2; mi++)
                #pragma unroll
                for (int ni = 0; ni < 8; ni++)
                    mma_tf32(acc[mi][ni][0], acc[mi][ni][1], acc[mi][ni][2], acc[mi][ni][3],
                             af[mi][0], af[mi][1], af[mi][2], af[mi][3],
                             bf[ni][0], bf[ni][1]);
        }
        __syncthreads();
    }

    // Epilogue: sigmoid(h+bu)·We, row partials
    float part[4] = {0.f, 0.f, 0.f, 0.f};
    #pragma unroll
    for (int mi = 0; mi < 2; mi++) {
        #pragma unroll
        for (int ni = 0; ni < 8; ni++) {
            const int c0 = wn * 64 + ni * 8 + t4 * 2;
            const int c1 = c0 + 1;
            const float w0 = sWe[c0], w1 = sWe[c1];
            const float b0 = sbu[c0], b1 = sbu[c1];
            float x;
            x = acc[mi][ni][0] + b0; part[mi * 2 + 0] += w0 / (1.f + __expf(-x));
            x = acc[mi][ni][1] + b1; part[mi * 2 + 0] += w1 / (1.f + __expf(-x));
            x = acc[mi][ni][2] + b0; part[mi * 2 + 1] += w0 / (1.f + __expf(-x));
            x = acc[mi][ni][3] + b1; part[mi * 2 + 1] += w1 / (1.f + __expf(-x));
        }
    }
    #pragma unroll
    for (int o = 1; o <= 2; o <<= 1)
        #pragma unroll
        for (int p = 0; p < 4; p++)
            part[p] += __shfl_xor_sync(0xffffffffu, part[p], o);
    if (t4 == 0) {
        #pragma unroll
        for (int p = 0; p < 4; p++) {
            int rl = wm * 32 + (p >> 1) * 16 + (p & 1) * 8 + g;
            ered[rl * 4 + wn] = part[p];
        }
    }
    __syncthreads();
    if (tid < 64) {
        int row = row0 + tid;
        if (row < n)
            g_e[row] = ered[tid * 4 + 0] + ered[tid * 4 + 1] + ered[tid * 4 + 2] + ered[tid * 4 + 3];
    }
}

// ---------------------------------------------------------------------------
// Segment softmax + weighted pooling. One block per segment.
// ---------------------------------------------------------------------------
__global__ __launch_bounds__(256) void pool_kernel(const float* __restrict__ feats, int b) {
    __shared__ float red[256];
    __shared__ float sex[256];
    const int seg = blockIdx.x;
    const int tid = threadIdx.x;
    const int base = g_off[seg];
    const int len  = g_off[seg + 1] - base;

    if (len <= 0) { g_rst[(size_t)seg * H + tid] = 0.f; return; }

    float m = -1e30f;
    for (int i = tid; i < len; i += 256) m = fmaxf(m, g_e[base + i]);
    red[tid] = m;
    __syncthreads();
    for (int o = 128; o > 0; o >>= 1) {
        if (tid < o) red[tid] = fmaxf(red[tid], red[tid + o]);
        __syncthreads();
    }
    m = red[0];
    __syncthreads();

    float d = 0.f;
    for (int i = tid; i < len; i += 256) d += __expf(g_e[base + i] - m);
    red[tid] = d;
    __syncthreads();
    for (int o = 128; o > 0; o >>= 1) {
        if (tid < o) red[tid] += red[tid + o];
        __syncthreads();
    }
    const float inv = 1.f / red[0];
    __syncthreads();

    float acc = 0.f;
    for (int s = 0; s < len; s += 256) {
        int c = len - s; if (c > 256) c = 256;
        sex[tid] = (tid < c) ? __expf(g_e[base + s + tid] - m) : 0.f;
        __syncthreads();
        #pragma unroll 4
        for (int i = 0; i < c; i++)
            acc += sex[i] * feats[(size_t)(base + s + i) * H + tid];
        __syncthreads();
    }
    g_rst[(size_t)seg * H + tid] = acc * inv;
}

// ---------------------------------------------------------------------------
// out = rst @ Wout.T, tf32 MMA, cp.async 2-stage. BM=32, BN=256, K=256.
// ---------------------------------------------------------------------------
#define A_ST_O (32 * PITCH)

__global__ __launch_bounds__(256, 2) void out_gemm_mma(
    float* __restrict__ out, const float* __restrict__ Wout, int m)
{
    extern __shared__ float sm[];
    float* As  = sm;                 // [2][A_ST_O]
    float* Bsm = sm + 2 * A_ST_O;    // [2][B_ST]

    const int tid  = threadIdx.x;
    const int lane = tid & 31;
    const int warp = tid >> 5;
    const int wm = warp >> 2;
    const int wn = warp & 3;
    const int g  = lane >> 2;
    const int t4 = lane & 3;
    const int row0 = blockIdx.x * 32;

    const uint32_t sAb = (uint32_t)__cvta_generic_to_shared(As);
    const uint32_t sBb = (uint32_t)__cvta_generic_to_shared(Bsm);

    float acc[8][4];
    #pragma unroll
    for (int ni = 0; ni < 8; ni++)
        #pragma unroll
        for (int q = 0; q < 4; q++) acc[ni][q] = 0.f;

    auto issue = [&](int buf, int k0) {
        {
            int ar = tid >> 3, kq = tid & 7;
            int grow = row0 + ar; if (grow >= m) grow = m - 1;
            cpa16(sAb + (uint32_t)(buf * A_ST_O + ar * PITCH + kq * 4) * 4u,
                  g_rst + (size_t)grow * H + k0 + kq * 4);
        }
        #pragma unroll
        for (int q = 0; q < 8; q++) {
            cpa16(sBb + (uint32_t)(buf * B_ST + tid * PITCH + q * 4) * 4u,
                  Wout + (size_t)tid * H + k0 + q * 4);
        }
        CP_COMMIT();
    };

    issue(0, 0);
    for (int s = 0; s < 8; s++) {
        if (s + 1 < 8) { issue((s + 1) & 1, (s + 1) * 32); CP_WAIT1(); }
        else           { CP_WAIT0(); }
        __syncthreads();

        const float* Ab = As  + (s & 1) * A_ST_O;
        const float* Bb = Bsm + (s & 1) * B_ST;

        #pragma unroll
        for (int ks = 0; ks < 4; ks++) {
            const int kb = ks * 8;
            const float* ab = Ab + (wm * 16) * PITCH;
            uint32_t a0 = __float_as_uint(ab[(g    ) * PITCH + kb + t4    ]);
            uint32_t a1 = __float_as_uint(ab[(g + 8) * PITCH + kb + t4    ]);
            uint32_t a2 = __float_as_uint(ab[(g    ) * PITCH + kb + t4 + 4]);
            uint32_t a3 = __float_as_uint(ab[(g + 8) * PITCH + kb + t4 + 4]);
            #pragma unroll
            for (int ni = 0; ni < 8; ni++) {
                const int nc = wn * 64 + ni * 8 + g;
                uint32_t b0 = __float_as_uint(Bb[nc * PITCH + kb + t4    ]);
                uint32_t b1 = __float_as_uint(Bb[nc * PITCH + kb + t4 + 4]);
                mma_tf32(acc[ni][0], acc[ni][1], acc[ni][2], acc[ni][3],
                         a0, a1, a2, a3, b0, b1);
            }
        }
        __syncthreads();
    }

    const int r0 = row0 + wm * 16 + g;
    const int r1 = r0 + 8;
    #pragma unroll
    for (int ni = 0; ni < 8; ni++) {
        const int c0 = wn * 64 + ni * 8 + t4 * 2;
        if (r0 < m) *(float2*)(out + (size_t)r0 * H + c0) = make_float2(acc[ni][0], acc[ni][1]);
        if (r1 < m) *(float2*)(out + (size_t)r1 * H + c0) = make_float2(acc[ni][2], acc[ni][3]);
    }
}

extern "C" void kernel_launch(void* const* d_in, const int* in_sizes, int n_in,
                              void* d_out, int out_size) {
    const float* feats = (const float*)d_in[0];
    const float* ctx   = (const float*)d_in[1];
    const void*  lens  = d_in[2];
    const float* Wu    = (const float*)d_in[3];
    const float* bu    = (const float*)d_in[4];
    const float* Wv    = (const float*)d_in[5];
    const float* We    = (const float*)d_in[6];
    const float* Wout  = (const float*)d_in[7];
    float* out = (float*)d_out;

    const int n = in_sizes[0] / H;
    const int b = out_size / H;

    const int smem_e   = (2 * A_ST + 2 * B_ST + H + H + 64 * 4) * 4;   // ~95 KB
    const int smem_out = (2 * A_ST_O + 2 * B_ST) * 4;                  // ~83 KB

    cudaFuncSetAttribute(e_gemm_mma,   cudaFuncAttributeMaxDynamicSharedMemorySize, smem_e);
    cudaFuncSetAttribute(out_gemm_mma, cudaFuncAttributeMaxDynamicSharedMemorySize, smem_out);

    scan_kernel<<<1, 1024>>>(lens, b, n);
    e_gemm_mma<<<(n + 63) / 64, 256, smem_e>>>(feats, ctx, Wu, Wv, bu, We, n);
    pool_kernel<<<b, 256>>>(feats, b);
    out_gemm_mma<<<(b + 31) / 32, 256, smem_out>>>(out, Wout, b);
}

// round 7
// speedup vs baseline: 4.9766x; 1.3482x over previous
#include <cuda_runtime.h>
#include <cuda_fp16.h>
#include <cstdint>

#define H 256
#define NMAX 204800
#define BMAX 4096

__device__ float  g_e[NMAX];
__device__ float  g_rst[BMAX * H];
__device__ int    g_off[BMAX + 1];
__device__ __half g_Ah[(size_t)NMAX * 512];   // [row][feats 0..255 | ctx 256..511]
__device__ __half g_Wh[256 * 512];            // [col j][Wu row j | Wv row j]
__device__ float  g_Wr[H * H];                // tf32-RNA rounded Wout

// ---------------------------------------------------------------------------
// helpers
// ---------------------------------------------------------------------------
__device__ __forceinline__ void cpa16(uint32_t dst, const void* src) {
    asm volatile("cp.async.cg.shared.global [%0], [%1], 16;\n" :: "r"(dst), "l"(src));
}
#define CP_COMMIT() asm volatile("cp.async.commit_group;\n" ::: "memory")
#define CP_WAIT0()  asm volatile("cp.async.wait_group 0;\n" ::: "memory")
#define CP_WAIT1()  asm volatile("cp.async.wait_group 1;\n" ::: "memory")

__device__ __forceinline__ void mma_f16(float& d0, float& d1, float& d2, float& d3,
                                        uint32_t a0, uint32_t a1, uint32_t a2, uint32_t a3,
                                        uint32_t b0, uint32_t b1) {
    asm volatile("mma.sync.aligned.m16n8k16.row.col.f32.f16.f16.f32 "
                 "{%0,%1,%2,%3},{%4,%5,%6,%7},{%8,%9},{%0,%1,%2,%3};\n"
                 : "+f"(d0), "+f"(d1), "+f"(d2), "+f"(d3)
                 : "r"(a0), "r"(a1), "r"(a2), "r"(a3), "r"(b0), "r"(b1));
}
__device__ __forceinline__ void mma_tf32(float& d0, float& d1, float& d2, float& d3,
                                         uint32_t a0, uint32_t a1, uint32_t a2, uint32_t a3,
                                         uint32_t b0, uint32_t b1) {
    asm volatile("mma.sync.aligned.m16n8k8.row.col.f32.tf32.tf32.f32 "
                 "{%0,%1,%2,%3},{%4,%5,%6,%7},{%8,%9},{%0,%1,%2,%3};\n"
                 : "+f"(d0), "+f"(d1), "+f"(d2), "+f"(d3)
                 : "r"(a0), "r"(a1), "r"(a2), "r"(a3), "r"(b0), "r"(b1));
}

// ---------------------------------------------------------------------------
// Prefix scan of ragged lengths (runtime int32/int64 detection).
// ---------------------------------------------------------------------------
__global__ __launch_bounds__(1024) void scan_kernel(const void* lens_raw, int b, int n_total) {
    __shared__ long long s[1024];
    __shared__ int use64;
    const int tid = threadIdx.x;
    const int* p32 = (const int*)lens_raw;

    long long local = 0;
    for (int i = tid; i < b; i += 1024) local += (long long)p32[i];
    s[tid] = local;
    __syncthreads();
    for (int o = 512; o > 0; o >>= 1) {
        if (tid < o) s[tid] += s[tid + o];
        __syncthreads();
    }
    if (tid == 0) use64 = (s[0] == (long long)n_total) ? 0 : 1;
    __syncthreads();
    const int u64 = use64;
    __syncthreads();

    const int PER = 4;
    long long v[PER];
    long long loc = 0;
    #pragma unroll
    for (int q = 0; q < PER; q++) {
        int i = tid * PER + q;
        long long val = 0;
        if (i < b) val = u64 ? ((const long long*)lens_raw)[i] : (long long)p32[i];
        v[q] = val;
        loc += val;
    }
    s[tid] = loc;
    __syncthreads();
    for (int o = 1; o < 1024; o <<= 1) {
        long long t = (tid >= o) ? s[tid - o] : 0;
        __syncthreads();
        s[tid] += t;
        __syncthreads();
    }
    long long run = s[tid] - loc;
    #pragma unroll
    for (int q = 0; q < PER; q++) {
        int i = tid * PER + q;
        if (i < b) {
            g_off[i] = (int)run;
            run += v[q];
            if (i == b - 1) g_off[b] = (int)run;
        }
    }
}

// ---------------------------------------------------------------------------
// Weight prep: fp16 [Wu|Wv] K-major per output col; tf32-RNA Wout.
// ---------------------------------------------------------------------------
__global__ __launch_bounds__(256) void conv_w_kernel(
    const float* __restrict__ Wu, const float* __restrict__ Wv, const float* __restrict__ Wout)
{
    const int j = blockIdx.x, k = threadIdx.x;
    g_Wh[j * 512 + k]       = __float2half_rn(Wu[j * H + k]);
    g_Wh[j * 512 + 256 + k] = __float2half_rn(Wv[j * H + k]);
    uint32_t c;
    asm("cvt.rna.tf32.f32 %0, %1;" : "=r"(c) : "f"(Wout[j * H + k]));
    g_Wr[j * H + k] = __uint_as_float(c);
}

// ---------------------------------------------------------------------------
// Input prep: fp16 [row][feats|ctx], 512 per row.
// ---------------------------------------------------------------------------
__global__ __launch_bounds__(256) void conv_in_kernel(
    const float* __restrict__ feats, const float* __restrict__ ctx, int nq)
{
    int q = blockIdx.x * 256 + threadIdx.x;   // one float4 (of feats and of ctx)
    if (q >= nq) return;
    int row = q >> 6, c4 = q & 63;
    float4 f = *(const float4*)(feats + (size_t)row * H + c4 * 4);
    float4 c = *(const float4*)(ctx   + (size_t)row * H + c4 * 4);
    __half2* d0 = (__half2*)(g_Ah + (size_t)row * 512 + c4 * 4);
    __half2* d1 = (__half2*)(g_Ah + (size_t)row * 512 + 256 + c4 * 4);
    d0[0] = __floats2half2_rn(f.x, f.y);
    d0[1] = __floats2half2_rn(f.z, f.w);
    d1[0] = __floats2half2_rn(c.x, c.y);
    d1[1] = __floats2half2_rn(c.z, c.w);
}

// ---------------------------------------------------------------------------
// Fused e-GEMM, fp16 m16n8k16 MMA, cp.async 2-stage.
// BM=128, BN=256, K=512, BK=32. 512 threads, 16 warps 4x4; warp tile 32x64.
// SMEM bytes: A bufs 2x10240 @0 | B bufs 2x20480 @20480 | sbu @61440 |
//             sWe @62464 | ered @63488 | total 65536.
// A/B tiles: pitch 40 halfs (20 words): fragment banks (20g+t4[+4])%32 distinct.
// ---------------------------------------------------------------------------
#define EPS_B   20480
#define EPS_BU  61440
#define EPS_WE  62464
#define EPS_ER  63488
#define EPS_TOT 65536

__global__ __launch_bounds__(512, 1) void e_gemm_f16(
    const float* __restrict__ bu, const float* __restrict__ We, int n)
{
    extern __shared__ char smc[];
    const uint32_t smb = (uint32_t)__cvta_generic_to_shared(smc);
    uint32_t* smw = (uint32_t*)smc;
    float* sbu  = (float*)(smc + EPS_BU);
    float* sWe  = (float*)(smc + EPS_WE);
    float* ered = (float*)(smc + EPS_ER);   // [128][4]

    const int tid  = threadIdx.x;
    const int lane = tid & 31;
    const int warp = tid >> 5;
    const int wm = warp >> 2;     // 0..3
    const int wn = warp & 3;      // 0..3
    const int g  = lane >> 2;     // 0..7
    const int t4 = lane & 3;      // 0..3
    const int row0 = blockIdx.x * 128;

    float acc[2][8][4];
    #pragma unroll
    for (int mi = 0; mi < 2; mi++)
        #pragma unroll
        for (int ni = 0; ni < 8; ni++)
            #pragma unroll
            for (int q = 0; q < 4; q++) acc[mi][ni][q] = 0.f;

    auto issue = [&](int buf, int sidx) {
        const int k0 = sidx * 32;
        {   // A: 128 rows x 4 chunks of 16B -> 512 chunks, 1/thread
            int r = tid >> 2, c = tid & 3;
            int grow = row0 + r; if (grow >= n) grow = n - 1;
            cpa16(smb + (uint32_t)(buf * 10240 + r * 80 + c * 16),
                  g_Ah + (size_t)grow * 512 + k0 + c * 8);
        }
        #pragma unroll
        for (int q = 0; q < 2; q++) {   // B: 256 cols x 4 chunks -> 1024, 2/thread
            int idx = tid + q * 512;
            int j = idx >> 2, c = idx & 3;
            cpa16(smb + (uint32_t)(EPS_B + buf * 20480 + j * 80 + c * 16),
                  g_Wh + (size_t)j * 512 + k0 + c * 8);
        }
        CP_COMMIT();
    };

    if (tid < 256) { sbu[tid] = bu[tid]; sWe[tid] = We[tid]; }

    issue(0, 0);
    for (int s = 0; s < 16; s++) {
        if (s + 1 < 16) { issue((s + 1) & 1, s + 1); CP_WAIT1(); }
        else            { CP_WAIT0(); }
        __syncthreads();

        const int abase = (s & 1) * 2560;            // words
        const int bbase = 5120 + (s & 1) * 5120;     // words

        #pragma unroll
        for (int kc = 0; kc < 2; kc++) {
            const int kw = kc * 8;
            uint32_t af[2][4];
            #pragma unroll
            for (int mi = 0; mi < 2; mi++) {
                const int rb = (wm * 32 + mi * 16) * 20 + abase + kw;
                af[mi][0] = smw[rb + g * 20 + t4];
                af[mi][1] = smw[rb + (g + 8) * 20 + t4];
                af[mi][2] = smw[rb + g * 20 + t4 + 4];
                af[mi][3] = smw[rb + (g + 8) * 20 + t4 + 4];
            }
            uint32_t bf[8][2];
            #pragma unroll
            for (int ni = 0; ni < 8; ni++) {
                const int nb = (wn * 64 + ni * 8 + g) * 20 + bbase + kw;
                bf[ni][0] = smw[nb + t4];
                bf[ni][1] = smw[nb + t4 + 4];
            }
            #pragma unroll
            for (int mi = 0; mi < 2; mi++)
                #pragma unroll
                for (int ni = 0; ni < 8; ni++)
                    mma_f16(acc[mi][ni][0], acc[mi][ni][1], acc[mi][ni][2], acc[mi][ni][3],
                            af[mi][0], af[mi][1], af[mi][2], af[mi][3],
                            bf[ni][0], bf[ni][1]);
        }
        __syncthreads();
    }

    // Epilogue: sigmoid(h+bu)·We, row partials across wn
    float part[4] = {0.f, 0.f, 0.f, 0.f};
    #pragma unroll
    for (int mi = 0; mi < 2; mi++) {
        #pragma unroll
        for (int ni = 0; ni < 8; ni++) {
            const int c0 = wn * 64 + ni * 8 + t4 * 2;
            const int c1 = c0 + 1;
            const float w0 = sWe[c0], w1 = sWe[c1];
            const float b0 = sbu[c0], b1 = sbu[c1];
            float x;
            x = acc[mi][ni][0] + b0; part[mi * 2 + 0] += w0 / (1.f + __expf(-x));
            x = acc[mi][ni][1] + b1; part[mi * 2 + 0] += w1 / (1.f + __expf(-x));
            x = acc[mi][ni][2] + b0; part[mi * 2 + 1] += w0 / (1.f + __expf(-x));
            x = acc[mi][ni][3] + b1; part[mi * 2 + 1] += w1 / (1.f + __expf(-x));
        }
    }
    #pragma unroll
    for (int o = 1; o <= 2; o <<= 1)
        #pragma unroll
        for (int p = 0; p < 4; p++)
            part[p] += __shfl_xor_sync(0xffffffffu, part[p], o);
    if (t4 == 0) {
        #pragma unroll
        for (int p = 0; p < 4; p++) {
            int rl = wm * 32 + (p >> 1) * 16 + (p & 1) * 8 + g;
            ered[rl * 4 + wn] = part[p];
        }
    }
    __syncthreads();
    if (tid < 128) {
        int row = row0 + tid;
        if (row < n)
            g_e[row] = ered[tid * 4 + 0] + ered[tid * 4 + 1] + ered[tid * 4 + 2] + ered[tid * 4 + 3];
    }
}

// ---------------------------------------------------------------------------
// Segment softmax + weighted pooling. One block per segment.
// ---------------------------------------------------------------------------
__global__ __launch_bounds__(256) void pool_kernel(const float* __restrict__ feats, int b) {
    __shared__ float red[256];
    __shared__ float sex[256];
    const int seg = blockIdx.x;
    const int tid = threadIdx.x;
    const int base = g_off[seg];
    const int len  = g_off[seg + 1] - base;

    if (len <= 0) { g_rst[(size_t)seg * H + tid] = 0.f; return; }

    float m = -1e30f;
    for (int i = tid; i < len; i += 256) m = fmaxf(m, g_e[base + i]);
    red[tid] = m;
    __syncthreads();
    for (int o = 128; o > 0; o >>= 1) {
        if (tid < o) red[tid] = fmaxf(red[tid], red[tid + o]);
        __syncthreads();
    }
    m = red[0];
    __syncthreads();

    float d = 0.f;
    for (int i = tid; i < len; i += 256) d += __expf(g_e[base + i] - m);
    red[tid] = d;
    __syncthreads();
    for (int o = 128; o > 0; o >>= 1) {
        if (tid < o) red[tid] += red[tid + o];
        __syncthreads();
    }
    const float inv = 1.f / red[0];
    __syncthreads();

    float acc = 0.f;
    for (int s = 0; s < len; s += 256) {
        int c = len - s; if (c > 256) c = 256;
        sex[tid] = (tid < c) ? __expf(g_e[base + s + tid] - m) : 0.f;
        __syncthreads();
        #pragma unroll 4
        for (int i = 0; i < c; i++)
            acc += sex[i] * feats[(size_t)(base + s + i) * H + tid];
        __syncthreads();
    }
    g_rst[(size_t)seg * H + tid] = acc * inv;
}

// ---------------------------------------------------------------------------
// out = rst @ Wout.T, tf32 SIMT MMA with cp.async (known good, 17us).
// ---------------------------------------------------------------------------
#define PITCH 36
#define B_ST  (256 * PITCH)
#define A_ST_O (32 * PITCH)

__global__ __launch_bounds__(256, 2) void out_gemm_mma(
    float* __restrict__ out, const float* __restrict__ Wout, int m)
{
    extern __shared__ float sm[];
    float* As  = sm;
    float* Bsm = sm + 2 * A_ST_O;

    const int tid  = threadIdx.x;
    const int lane = tid & 31;
    const int warp = tid >> 5;
    const int wm = warp >> 2;
    const int wn = warp & 3;
    const int g  = lane >> 2;
    const int t4 = lane & 3;
    const int row0 = blockIdx.x * 32;

    const uint32_t sAb = (uint32_t)__cvta_generic_to_shared(As);
    const uint32_t sBb = (uint32_t)__cvta_generic_to_shared(Bsm);

    float acc[8][4];
    #pragma unroll
    for (int ni = 0; ni < 8; ni++)
        #pragma unroll
        for (int q = 0; q < 4; q++) acc[ni][q] = 0.f;

    auto issue = [&](int buf, int k0) {
        {
            int ar = tid >> 3, kq = tid & 7;
            int grow = row0 + ar; if (grow >= m) grow = m - 1;
            cpa16(sAb + (uint32_t)(buf * A_ST_O + ar * PITCH + kq * 4) * 4u,
                  g_rst + (size_t)grow * H + k0 + kq * 4);
        }
        #pragma unroll
        for (int q = 0; q < 8; q++) {
            cpa16(sBb + (uint32_t)(buf * B_ST + tid * PITCH + q * 4) * 4u,
                  Wout + (size_t)tid * H + k0 + q * 4);
        }
        CP_COMMIT();
    };

    issue(0, 0);
    for (int s = 0; s < 8; s++) {
        if (s + 1 < 8) { issue((s + 1) & 1, (s + 1) * 32); CP_WAIT1(); }
        else           { CP_WAIT0(); }
        __syncthreads();

        const float* Ab = As  + (s & 1) * A_ST_O;
        const float* Bb = Bsm + (s & 1) * B_ST;

        #pragma unroll
        for (int ks = 0; ks < 4; ks++) {
            const int kb = ks * 8;
            const float* ab = Ab + (wm * 16) * PITCH;
            uint32_t a0 = __float_as_uint(ab[(g    ) * PITCH + kb + t4    ]);
            uint32_t a1 = __float_as_uint(ab[(g + 8) * PITCH + kb + t4    ]);
            uint32_t a2 = __float_as_uint(ab[(g    ) * PITCH + kb + t4 + 4]);
            uint32_t a3 = __float_as_uint(ab[(g + 8) * PITCH + kb + t4 + 4]);
            #pragma unroll
            for (int ni = 0; ni < 8; ni++) {
                const int nc = wn * 64 + ni * 8 + g;
                uint32_t b0 = __float_as_uint(Bb[nc * PITCH + kb + t4    ]);
                uint32_t b1 = __float_as_uint(Bb[nc * PITCH + kb + t4 + 4]);
                mma_tf32(acc[ni][0], acc[ni][1], acc[ni][2], acc[ni][3],
                         a0, a1, a2, a3, b0, b1);
            }
        }
        __syncthreads();
    }

    const int r0 = row0 + wm * 16 + g;
    const int r1 = r0 + 8;
    #pragma unroll
    for (int ni = 0; ni < 8; ni++) {
        const int c0 = wn * 64 + ni * 8 + t4 * 2;
        if (r0 < m) *(float2*)(out + (size_t)r0 * H + c0) = make_float2(acc[ni][0], acc[ni][1]);
        if (r1 < m) *(float2*)(out + (size_t)r1 * H + c0) = make_float2(acc[ni][2], acc[ni][3]);
    }
}

extern "C" void kernel_launch(void* const* d_in, const int* in_sizes, int n_in,
                              void* d_out, int out_size) {
    const float* feats = (const float*)d_in[0];
    const float* ctx   = (const float*)d_in[1];
    const void*  lens  = d_in[2];
    const float* Wu    = (const float*)d_in[3];
    const float* bu    = (const float*)d_in[4];
    const float* Wv    = (const float*)d_in[5];
    const float* We    = (const float*)d_in[6];
    const float* Wout  = (const float*)d_in[7];
    float* out = (float*)d_out;

    const int n = in_sizes[0] / H;
    const int b = out_size / H;

    const int smem_out = (2 * A_ST_O + 2 * B_ST) * 4;
    cudaFuncSetAttribute(e_gemm_f16,   cudaFuncAttributeMaxDynamicSharedMemorySize, EPS_TOT);
    cudaFuncSetAttribute(out_gemm_mma, cudaFuncAttributeMaxDynamicSharedMemorySize, smem_out);

    float* Wout_r = nullptr; cudaGetSymbolAddress((void**)&Wout_r, g_Wr);

    const int nq = n * 64;   // float4 quads per input matrix
    scan_kernel<<<1, 1024>>>(lens, b, n);
    conv_w_kernel<<<256, 256>>>(Wu, Wv, Wout);
    conv_in_kernel<<<(nq + 255) / 256, 256>>>(feats, ctx, nq);
    e_gemm_f16<<<(n + 127) / 128, 512, EPS_TOT>>>(bu, We, n);
    pool_kernel<<<b, 256>>>(feats, b);
    out_gemm_mma<<<(b + 31) / 32, 256, smem_out>>>(out, Wout_r, b);
}

// round 9
// speedup vs baseline: 8.3981x; 1.6875x over previous
#include <cuda_runtime.h>
#include <cuda_fp16.h>
#include <cstdint>
#include <cstring>

#define H 256
#define NMAX 204800
#define BMAX 4096

__device__ float  g_e[NMAX];
__device__ float  g_rst[BMAX * H];
__device__ int    g_off[BMAX + 1];
__device__ __half g_Wh[256 * 512];   // [col j][Wu row j (k 0..255) | Wv row j (k 256..511)]
__device__ float  g_Wr[H * H];       // tf32-RNA rounded Wout

// ---------------------------------------------------------------------------
// helpers
// ---------------------------------------------------------------------------
__device__ __forceinline__ uint32_t h2u(__half2 h) {
    uint32_t u;
    memcpy(&u, &h, 4);
    return u;
}
__device__ __forceinline__ void cpa16(uint32_t dst, const void* src) {
    asm volatile("cp.async.cg.shared.global [%0], [%1], 16;\n" :: "r"(dst), "l"(src));
}
#define CP_COMMIT() asm volatile("cp.async.commit_group;\n" ::: "memory")
#define CP_WAIT0()  asm volatile("cp.async.wait_group 0;\n" ::: "memory")
#define CP_WAIT1()  asm volatile("cp.async.wait_group 1;\n" ::: "memory")

__device__ __forceinline__ void mma_f16(float& d0, float& d1, float& d2, float& d3,
                                        uint32_t a0, uint32_t a1, uint32_t a2, uint32_t a3,
                                        uint32_t b0, uint32_t b1) {
    asm volatile("mma.sync.aligned.m16n8k16.row.col.f32.f16.f16.f32 "
                 "{%0,%1,%2,%3},{%4,%5,%6,%7},{%8,%9},{%0,%1,%2,%3};\n"
                 : "+f"(d0), "+f"(d1), "+f"(d2), "+f"(d3)
                 : "r"(a0), "r"(a1), "r"(a2), "r"(a3), "r"(b0), "r"(b1));
}
__device__ __forceinline__ void mma_tf32(float& d0, float& d1, float& d2, float& d3,
                                         uint32_t a0, uint32_t a1, uint32_t a2, uint32_t a3,
                                         uint32_t b0, uint32_t b1) {
    asm volatile("mma.sync.aligned.m16n8k8.row.col.f32.tf32.tf32.f32 "
                 "{%0,%1,%2,%3},{%4,%5,%6,%7},{%8,%9},{%0,%1,%2,%3};\n"
                 : "+f"(d0), "+f"(d1), "+f"(d2), "+f"(d3)
                 : "r"(a0), "r"(a1), "r"(a2), "r"(a3), "r"(b0), "r"(b1));
}
__device__ __forceinline__ void ldsm_x4(uint32_t& r0, uint32_t& r1, uint32_t& r2, uint32_t& r3,
                                        uint32_t addr) {
    asm volatile("ldmatrix.sync.aligned.m8n8.x4.shared.b16 {%0,%1,%2,%3}, [%4];"
                 : "=r"(r0), "=r"(r1), "=r"(r2), "=r"(r3) : "r"(addr));
}

// ---------------------------------------------------------------------------
// Prefix scan of ragged lengths (runtime int32/int64 detection).
// ---------------------------------------------------------------------------
__global__ __launch_bounds__(1024) void scan_kernel(const void* lens_raw, int b, int n_total) {
    __shared__ long long s[1024];
    __shared__ int use64;
    const int tid = threadIdx.x;
    const int* p32 = (const int*)lens_raw;

    long long local = 0;
    for (int i = tid; i < b; i += 1024) local += (long long)p32[i];
    s[tid] = local;
    __syncthreads();
    for (int o = 512; o > 0; o >>= 1) {
        if (tid < o) s[tid] += s[tid + o];
        __syncthreads();
    }
    if (tid == 0) use64 = (s[0] == (long long)n_total) ? 0 : 1;
    __syncthreads();
    const int u64 = use64;
    __syncthreads();

    const int PER = 4;
    long long v[PER];
    long long loc = 0;
    #pragma unroll
    for (int q = 0; q < PER; q++) {
        int i = tid * PER + q;
        long long val = 0;
        if (i < b) val = u64 ? ((const long long*)lens_raw)[i] : (long long)p32[i];
        v[q] = val;
        loc += val;
    }
    s[tid] = loc;
    __syncthreads();
    for (int o = 1; o < 1024; o <<= 1) {
        long long t = (tid >= o) ? s[tid - o] : 0;
        __syncthreads();
        s[tid] += t;
        __syncthreads();
    }
    long long run = s[tid] - loc;
    #pragma unroll
    for (int q = 0; q < PER; q++) {
        int i = tid * PER + q;
        if (i < b) {
            g_off[i] = (int)run;
            run += v[q];
            if (i == b - 1) g_off[b] = (int)run;
        }
    }
}

// ---------------------------------------------------------------------------
// Weight prep: fp16 [Wu|Wv] K-major per output col; tf32-RNA Wout.
// ---------------------------------------------------------------------------
__global__ __launch_bounds__(256) void conv_w_kernel(
    const float* __restrict__ Wu, const float* __restrict__ Wv, const float* __restrict__ Wout)
{
    const int j = blockIdx.x, k = threadIdx.x;
    g_Wh[j * 512 + k]       = __float2half_rn(Wu[j * H + k]);
    g_Wh[j * 512 + 256 + k] = __float2half_rn(Wv[j * H + k]);
    uint32_t c;
    asm("cvt.rna.tf32.f32 %0, %1;" : "=r"(c) : "f"(Wout[j * H + k]));
    g_Wr[j * H + k] = __uint_as_float(c);
}

// ---------------------------------------------------------------------------
// Fused e-GEMM, fp16 m16n8k16, LDSM fragments, fp32 A loaded+converted inline.
// BM=128, BN=256, K=512, BK=32. 512 threads, 16 warps 4x4; warp tile 32x64.
// SMEM: A bufs 2x10240 @0 | B bufs 2x20480 @20480 | sbu @61440 | sWe @62464 |
//       ered @63488 | total 65536. Tiles pitch 40 halfs (80 B).
// ---------------------------------------------------------------------------
#define EPS_B   20480
#define EPS_BU  61440
#define EPS_WE  62464
#define EPS_ER  63488
#define EPS_TOT 65536

__global__ __launch_bounds__(512, 1) void e_gemm_f16(
    const float* __restrict__ feats, const float* __restrict__ ctx,
    const float* __restrict__ bu, const float* __restrict__ We, int n)
{
    extern __shared__ char smc[];
    const uint32_t smb = (uint32_t)__cvta_generic_to_shared(smc);
    float* sbu  = (float*)(smc + EPS_BU);
    float* sWe  = (float*)(smc + EPS_WE);
    float* ered = (float*)(smc + EPS_ER);   // [128][4]

    const int tid  = threadIdx.x;
    const int lane = tid & 31;
    const int warp = tid >> 5;
    const int wm = warp >> 2;     // 0..3
    const int wn = warp & 3;      // 0..3
    const int g  = lane >> 2;     // 0..7
    const int t4 = lane & 3;      // 0..3
    const int row0 = blockIdx.x * 128;

    // A loader indices: thread -> row r (0..127), k-chunk c (0..3) of 8 halfs
    const int ar = tid >> 2;
    const int ac = tid & 3;
    int arow = row0 + ar; if (arow >= n) arow = n - 1;

    float acc[2][8][4];
    #pragma unroll
    for (int mi = 0; mi < 2; mi++)
        #pragma unroll
        for (int ni = 0; ni < 8; ni++)
            #pragma unroll
            for (int q = 0; q < 4; q++) acc[mi][ni][q] = 0.f;

    float4 avA, avB;   // next-stage A data (8 fp32)

    auto ldgA = [&](int sidx) {
        const int k0 = sidx * 32;
        const float* Ap = (k0 < 256) ? feats : ctx;
        const float* p = Ap + (size_t)arow * H + (k0 & 255) + ac * 8;
        avA = *(const float4*)p;
        avB = *(const float4*)(p + 4);
    };
    auto stsA = [&](int buf) {
        uint4 u;
        u.x = h2u(__floats2half2_rn(avA.x, avA.y));
        u.y = h2u(__floats2half2_rn(avA.z, avA.w));
        u.z = h2u(__floats2half2_rn(avB.x, avB.y));
        u.w = h2u(__floats2half2_rn(avB.z, avB.w));
        *(uint4*)(smc + buf * 10240 + ar * 80 + ac * 16) = u;
    };
    auto issueB = [&](int buf, int sidx) {
        const int k0 = sidx * 32;
        #pragma unroll
        for (int q = 0; q < 2; q++) {
            int idx = tid + q * 512;
            int j = idx >> 2, c = idx & 3;
            cpa16(smb + (uint32_t)(EPS_B + buf * 20480 + j * 80 + c * 16),
                  g_Wh + (size_t)j * 512 + k0 + c * 8);
        }
        CP_COMMIT();
    };

    // LDSM addresses (byte offsets within a tile)
    const int a_row_in = (lane & 15);
    const int a_koff   = (lane >> 4) * 8;
    const int b_col_in = ((lane >> 4) & 1) * 8 + (lane & 7);
    const int b_koff   = ((lane >> 3) & 1) * 8;

    ldgA(0); stsA(0);
    issueB(0, 0);
    if (tid < 256) { sbu[tid] = bu[tid]; sWe[tid] = We[tid]; }

    for (int s = 0; s < 16; s++) {
        if (s + 1 < 16) { ldgA(s + 1); issueB((s + 1) & 1, s + 1); CP_WAIT1(); }
        else            { CP_WAIT0(); }
        __syncthreads();

        const uint32_t abase = smb + (s & 1) * 10240;
        const uint32_t bbase = smb + EPS_B + (s & 1) * 20480;

        #pragma unroll
        for (int kc = 0; kc < 2; kc++) {
            const int kw = kc * 16;
            uint32_t af[2][4];
            #pragma unroll
            for (int mi = 0; mi < 2; mi++) {
                ldsm_x4(af[mi][0], af[mi][1], af[mi][2], af[mi][3],
                        abase + (uint32_t)((wm * 32 + mi * 16 + a_row_in) * 80
                                           + (kw + a_koff) * 2));
            }
            uint32_t bf[8][2];
            #pragma unroll
            for (int n2 = 0; n2 < 4; n2++) {
                ldsm_x4(bf[n2 * 2][0], bf[n2 * 2][1], bf[n2 * 2 + 1][0], bf[n2 * 2 + 1][1],
                        bbase + (uint32_t)((wn * 64 + n2 * 16 + b_col_in) * 80
                                           + (kw + b_koff) * 2));
            }
            #pragma unroll
            for (int mi = 0; mi < 2; mi++)
                #pragma unroll
                for (int ni = 0; ni < 8; ni++)
                    mma_f16(acc[mi][ni][0], acc[mi][ni][1], acc[mi][ni][2], acc[mi][ni][3],
                            af[mi][0], af[mi][1], af[mi][2], af[mi][3],
                            bf[ni][0], bf[ni][1]);
        }
        if (s + 1 < 16) stsA((s + 1) & 1);
    }

    // Epilogue: sigmoid(h+bu)·We, row partials across wn
    float part[4] = {0.f, 0.f, 0.f, 0.f};
    #pragma unroll
    for (int mi = 0; mi < 2; mi++) {
        #pragma unroll
        for (int ni = 0; ni < 8; ni++) {
            const int c0 = wn * 64 + ni * 8 + t4 * 2;
            const int c1 = c0 + 1;
            const float w0 = sWe[c0], w1 = sWe[c1];
            const float b0 = sbu[c0], b1 = sbu[c1];
            float x;
            x = acc[mi][ni][0] + b0; part[mi * 2 + 0] += w0 / (1.f + __expf(-x));
            x = acc[mi][ni][1] + b1; part[mi * 2 + 0] += w1 / (1.f + __expf(-x));
            x = acc[mi][ni][2] + b0; part[mi * 2 + 1] += w0 / (1.f + __expf(-x));
            x = acc[mi][ni][3] + b1; part[mi * 2 + 1] += w1 / (1.f + __expf(-x));
        }
    }
    #pragma unroll
    for (int o = 1; o <= 2; o <<= 1)
        #pragma unroll
        for (int p = 0; p < 4; p++)
            part[p] += __shfl_xor_sync(0xffffffffu, part[p], o);
    if (t4 == 0) {
        #pragma unroll
        for (int p = 0; p < 4; p++) {
            int rl = wm * 32 + (p >> 1) * 16 + (p & 1) * 8 + g;
            ered[rl * 4 + wn] = part[p];
        }
    }
    __syncthreads();
    if (tid < 128) {
        int row = row0 + tid;
        if (row < n)
            g_e[row] = ered[tid * 4 + 0] + ered[tid * 4 + 1] + ered[tid * 4 + 2] + ered[tid * 4 + 3];
    }
}

// ---------------------------------------------------------------------------
// Segment softmax + pooling: float4 columns, 4 rows in flight.
// ---------------------------------------------------------------------------
__global__ __launch_bounds__(256) void pool_kernel(const float* __restrict__ feats, int b) {
    __shared__ float red[256];
    __shared__ float sex[256];
    __shared__ float red4[4 * 256];
    const int seg = blockIdx.x;
    const int tid = threadIdx.x;
    const int base = g_off[seg];
    const int len  = g_off[seg + 1] - base;

    if (len <= 0) { g_rst[(size_t)seg * H + tid] = 0.f; return; }

    float m = -1e30f;
    for (int i = tid; i < len; i += 256) m = fmaxf(m, g_e[base + i]);
    red[tid] = m;
    __syncthreads();
    for (int o = 128; o > 0; o >>= 1) {
        if (tid < o) red[tid] = fmaxf(red[tid], red[tid + o]);
        __syncthreads();
    }
    m = red[0];
    __syncthreads();

    float d = 0.f;
    for (int i = tid; i < len; i += 256) d += __expf(g_e[base + i] - m);
    red[tid] = d;
    __syncthreads();
    for (int o = 128; o > 0; o >>= 1) {
        if (tid < o) red[tid] += red[tid + o];
        __syncthreads();
    }
    const float inv = 1.f / red[0];
    __syncthreads();

    // thread: row-group r4 (0..3), column quad cq (0..63)
    const int r4 = tid >> 6;
    const int cq = tid & 63;
    float4 acc = make_float4(0.f, 0.f, 0.f, 0.f);
    for (int s = 0; s < len; s += 256) {
        int c = len - s; if (c > 256) c = 256;
        sex[tid] = (tid < c) ? __expf(g_e[base + s + tid] - m) : 0.f;
        __syncthreads();
        for (int i = r4; i < c; i += 4) {
            float w = sex[i];
            float4 v = *(const float4*)(feats + (size_t)(base + s + i) * H + cq * 4);
            acc.x += w * v.x; acc.y += w * v.y; acc.z += w * v.z; acc.w += w * v.w;
        }
        __syncthreads();
    }
    *(float4*)(red4 + r4 * 256 + cq * 4) = acc;
    __syncthreads();
    float val = red4[tid] + red4[256 + tid] + red4[512 + tid] + red4[768 + tid];
    g_rst[(size_t)seg * H + tid] = val * inv;
}

// ---------------------------------------------------------------------------
// out = rst @ Wout.T, tf32 SIMT MMA with cp.async (known good, 17us).
// ---------------------------------------------------------------------------
#define PITCH 36
#define B_ST  (256 * PITCH)
#define A_ST_O (32 * PITCH)

__global__ __launch_bounds__(256, 2) void out_gemm_mma(
    float* __restrict__ out, const float* __restrict__ Wout, int m)
{
    extern __shared__ float sm[];
    float* As  = sm;
    float* Bsm = sm + 2 * A_ST_O;

    const int tid  = threadIdx.x;
    const int lane = tid & 31;
    const int warp = tid >> 5;
    const int wm = warp >> 2;
    const int wn = warp & 3;
    const int g  = lane >> 2;
    const int t4 = lane & 3;
    const int row0 = blockIdx.x * 32;

    const uint32_t sAb = (uint32_t)__cvta_generic_to_shared(As);
    const uint32_t sBb = (uint32_t)__cvta_generic_to_shared(Bsm);

    float acc[8][4];
    #pragma unroll
    for (int ni = 0; ni < 8; ni++)
        #pragma unroll
        for (int q = 0; q < 4; q++) acc[ni][q] = 0.f;

    auto issue = [&](int buf, int k0) {
        {
            int ar = tid >> 3, kq = tid & 7;
            int grow = row0 + ar; if (grow >= m) grow = m - 1;
            cpa16(sAb + (uint32_t)(buf * A_ST_O + ar * PITCH + kq * 4) * 4u,
                  g_rst + (size_t)grow * H + k0 + kq * 4);
        }
        #pragma unroll
        for (int q = 0; q < 8; q++) {
            cpa16(sBb + (uint32_t)(buf * B_ST + tid * PITCH + q * 4) * 4u,
                  Wout + (size_t)tid * H + k0 + q * 4);
        }
        CP_COMMIT();
    };

    issue(0, 0);
    for (int s = 0; s < 8; s++) {
        if (s + 1 < 8) { issue((s + 1) & 1, (s + 1) * 32); CP_WAIT1(); }
        else           { CP_WAIT0(); }
        __syncthreads();

        const float* Ab = As  + (s & 1) * A_ST_O;
        const float* Bb = Bsm + (s & 1) * B_ST;

        #pragma unroll
        for (int ks = 0; ks < 4; ks++) {
            const int kb = ks * 8;
            const float* ab = Ab + (wm * 16) * PITCH;
            uint32_t a0 = __float_as_uint(ab[(g    ) * PITCH + kb + t4    ]);
            uint32_t a1 = __float_as_uint(ab[(g + 8) * PITCH + kb + t4    ]);
            uint32_t a2 = __float_as_uint(ab[(g    ) * PITCH + kb + t4 + 4]);
            uint32_t a3 = __float_as_uint(ab[(g + 8) * PITCH + kb + t4 + 4]);
            #pragma unroll
            for (int ni = 0; ni < 8; ni++) {
                const int nc = wn * 64 + ni * 8 + g;
                uint32_t b0 = __float_as_uint(Bb[nc * PITCH + kb + t4    ]);
                uint32_t b1 = __float_as_uint(Bb[nc * PITCH + kb + t4 + 4]);
                mma_tf32(acc[ni][0], acc[ni][1], acc[ni][2], acc[ni][3],
                         a0, a1, a2, a3, b0, b1);
            }
        }
        __syncthreads();
    }

    const int r0 = row0 + wm * 16 + g;
    const int r1 = r0 + 8;
    #pragma unroll
    for (int ni = 0; ni < 8; ni++) {
        const int c0 = wn * 64 + ni * 8 + t4 * 2;
        if (r0 < m) *(float2*)(out + (size_t)r0 * H + c0) = make_float2(acc[ni][0], acc[ni][1]);
        if (r1 < m) *(float2*)(out + (size_t)r1 * H + c0) = make_float2(acc[ni][2], acc[ni][3]);
    }
}

extern "C" void kernel_launch(void* const* d_in, const int* in_sizes, int n_in,
                              void* d_out, int out_size) {
    const float* feats = (const float*)d_in[0];
    const float* ctx   = (const float*)d_in[1];
    const void*  lens  = d_in[2];
    const float* Wu    = (const float*)d_in[3];
    const float* bu    = (const float*)d_in[4];
    const float* Wv    = (const float*)d_in[5];
    const float* We    = (const float*)d_in[6];
    const float* Wout  = (const float*)d_in[7];
    float* out = (float*)d_out;

    const int n = in_sizes[0] / H;
    const int b = out_size / H;

    const int smem_out = (2 * A_ST_O + 2 * B_ST) * 4;
    cudaFuncSetAttribute(e_gemm_f16,   cudaFuncAttributeMaxDynamicSharedMemorySize, EPS_TOT);
    cudaFuncSetAttribute(out_gemm_mma, cudaFuncAttributeMaxDynamicSharedMemorySize, smem_out);

    float* Wout_r = nullptr; cudaGetSymbolAddress((void**)&Wout_r, g_Wr);

    scan_kernel<<<1, 1024>>>(lens, b, n);
    conv_w_kernel<<<256, 256>>>(Wu, Wv, Wout);
    e_gemm_f16<<<(n + 127) / 128, 512, EPS_TOT>>>(feats, ctx, bu, We, n);
    pool_kernel<<<b, 256>>>(feats, b);
    out_gemm_mma<<<(b + 31) / 32, 256, smem_out>>>(out, Wout_r, b);
}

// round 10
// speedup vs baseline: 10.1001x; 1.2027x over previous
#include <cuda_runtime.h>
#include <cuda_fp16.h>
#include <cstdint>
#include <cstring>

#define H 256
#define NMAX 204800
#define BMAX 4096

__device__ float  g_e[NMAX];
__device__ float  g_rst[BMAX * H];
__device__ int    g_off[BMAX + 1];
__device__ __half g_Wh[256 * 512];   // [col j][Wu row j (k 0..255) | Wv row j (k 256..511)]
__device__ float  g_Wr[H * H];       // tf32-RNA rounded Wout

// ---------------------------------------------------------------------------
// helpers
// ---------------------------------------------------------------------------
__device__ __forceinline__ uint32_t h2u(__half2 h) {
    uint32_t u;
    memcpy(&u, &h, 4);
    return u;
}
__device__ __forceinline__ void cpa16(uint32_t dst, const void* src) {
    asm volatile("cp.async.cg.shared.global [%0], [%1], 16;\n" :: "r"(dst), "l"(src));
}
#define CP_COMMIT() asm volatile("cp.async.commit_group;\n" ::: "memory")
#define CP_WAIT0()  asm volatile("cp.async.wait_group 0;\n" ::: "memory")
#define CP_WAIT1()  asm volatile("cp.async.wait_group 1;\n" ::: "memory")

__device__ __forceinline__ void mma_f16(float& d0, float& d1, float& d2, float& d3,
                                        uint32_t a0, uint32_t a1, uint32_t a2, uint32_t a3,
                                        uint32_t b0, uint32_t b1) {
    asm volatile("mma.sync.aligned.m16n8k16.row.col.f32.f16.f16.f32 "
                 "{%0,%1,%2,%3},{%4,%5,%6,%7},{%8,%9},{%0,%1,%2,%3};\n"
                 : "+f"(d0), "+f"(d1), "+f"(d2), "+f"(d3)
                 : "r"(a0), "r"(a1), "r"(a2), "r"(a3), "r"(b0), "r"(b1));
}
__device__ __forceinline__ void mma_tf32(float& d0, float& d1, float& d2, float& d3,
                                         uint32_t a0, uint32_t a1, uint32_t a2, uint32_t a3,
                                         uint32_t b0, uint32_t b1) {
    asm volatile("mma.sync.aligned.m16n8k8.row.col.f32.tf32.tf32.f32 "
                 "{%0,%1,%2,%3},{%4,%5,%6,%7},{%8,%9},{%0,%1,%2,%3};\n"
                 : "+f"(d0), "+f"(d1), "+f"(d2), "+f"(d3)
                 : "r"(a0), "r"(a1), "r"(a2), "r"(a3), "r"(b0), "r"(b1));
}
__device__ __forceinline__ void ldsm_x4(uint32_t& r0, uint32_t& r1, uint32_t& r2, uint32_t& r3,
                                        uint32_t addr) {
    asm volatile("ldmatrix.sync.aligned.m8n8.x4.shared.b16 {%0,%1,%2,%3}, [%4];"
                 : "=r"(r0), "=r"(r1), "=r"(r2), "=r"(r3) : "r"(addr));
}

// ---------------------------------------------------------------------------
// Prefix scan of ragged lengths (runtime int32/int64 detection).
// ---------------------------------------------------------------------------
__global__ __launch_bounds__(1024) void scan_kernel(const void* lens_raw, int b, int n_total) {
    __shared__ long long s[1024];
    __shared__ int use64;
    const int tid = threadIdx.x;
    const int* p32 = (const int*)lens_raw;

    long long local = 0;
    for (int i = tid; i < b; i += 1024) local += (long long)p32[i];
    s[tid] = local;
    __syncthreads();
    for (int o = 512; o > 0; o >>= 1) {
        if (tid < o) s[tid] += s[tid + o];
        __syncthreads();
    }
    if (tid == 0) use64 = (s[0] == (long long)n_total) ? 0 : 1;
    __syncthreads();
    const int u64 = use64;
    __syncthreads();

    const int PER = 4;
    long long v[PER];
    long long loc = 0;
    #pragma unroll
    for (int q = 0; q < PER; q++) {
        int i = tid * PER + q;
        long long val = 0;
        if (i < b) val = u64 ? ((const long long*)lens_raw)[i] : (long long)p32[i];
        v[q] = val;
        loc += val;
    }
    s[tid] = loc;
    __syncthreads();
    for (int o = 1; o < 1024; o <<= 1) {
        long long t = (tid >= o) ? s[tid - o] : 0;
        __syncthreads();
        s[tid] += t;
        __syncthreads();
    }
    long long run = s[tid] - loc;
    #pragma unroll
    for (int q = 0; q < PER; q++) {
        int i = tid * PER + q;
        if (i < b) {
            g_off[i] = (int)run;
            run += v[q];
            if (i == b - 1) g_off[b] = (int)run;
        }
    }
}

// ---------------------------------------------------------------------------
// Weight prep: fp16 [Wu|Wv] K-major per output col; tf32-RNA Wout.
// ---------------------------------------------------------------------------
__global__ __launch_bounds__(256) void conv_w_kernel(
    const float* __restrict__ Wu, const float* __restrict__ Wv, const float* __restrict__ Wout)
{
    const int j = blockIdx.x, k = threadIdx.x;
    g_Wh[j * 512 + k]       = __float2half_rn(Wu[j * H + k]);
    g_Wh[j * 512 + 256 + k] = __float2half_rn(Wv[j * H + k]);
    uint32_t c;
    asm("cvt.rna.tf32.f32 %0, %1;" : "=r"(c) : "f"(Wout[j * H + k]));
    g_Wr[j * H + k] = __uint_as_float(c);
}

// ---------------------------------------------------------------------------
// Fused e-GEMM, fp16 m16n8k16, LDSM fragments, fp32 A loaded+converted inline.
// BM=128, BN=256, K=512, BK=32. 512 threads, 16 warps 4x4; warp tile 32x64.
// SMEM: A bufs 2x10240 @0 | B bufs 2x20480 @20480 | sbu @61440 | sWe @62464 |
//       ered @63488 | total 65536. Tiles pitch 40 halfs (80 B).
// ---------------------------------------------------------------------------
#define EPS_B   20480
#define EPS_BU  61440
#define EPS_WE  62464
#define EPS_ER  63488
#define EPS_TOT 65536

__global__ __launch_bounds__(512, 1) void e_gemm_f16(
    const float* __restrict__ feats, const float* __restrict__ ctx,
    const float* __restrict__ bu, const float* __restrict__ We, int n)
{
    extern __shared__ char smc[];
    const uint32_t smb = (uint32_t)__cvta_generic_to_shared(smc);
    float* sbu  = (float*)(smc + EPS_BU);
    float* sWe  = (float*)(smc + EPS_WE);
    float* ered = (float*)(smc + EPS_ER);   // [128][4]

    const int tid  = threadIdx.x;
    const int lane = tid & 31;
    const int warp = tid >> 5;
    const int wm = warp >> 2;     // 0..3
    const int wn = warp & 3;      // 0..3
    const int g  = lane >> 2;     // 0..7
    const int t4 = lane & 3;      // 0..3
    const int row0 = blockIdx.x * 128;

    const int ar = tid >> 2;
    const int ac = tid & 3;
    int arow = row0 + ar; if (arow >= n) arow = n - 1;

    float acc[2][8][4];
    #pragma unroll
    for (int mi = 0; mi < 2; mi++)
        #pragma unroll
        for (int ni = 0; ni < 8; ni++)
            #pragma unroll
            for (int q = 0; q < 4; q++) acc[mi][ni][q] = 0.f;

    float4 avA, avB;

    auto ldgA = [&](int sidx) {
        const int k0 = sidx * 32;
        const float* Ap = (k0 < 256) ? feats : ctx;
        const float* p = Ap + (size_t)arow * H + (k0 & 255) + ac * 8;
        avA = *(const float4*)p;
        avB = *(const float4*)(p + 4);
    };
    auto stsA = [&](int buf) {
        uint4 u;
        u.x = h2u(__floats2half2_rn(avA.x, avA.y));
        u.y = h2u(__floats2half2_rn(avA.z, avA.w));
        u.z = h2u(__floats2half2_rn(avB.x, avB.y));
        u.w = h2u(__floats2half2_rn(avB.z, avB.w));
        *(uint4*)(smc + buf * 10240 + ar * 80 + ac * 16) = u;
    };
    auto issueB = [&](int buf, int sidx) {
        const int k0 = sidx * 32;
        #pragma unroll
        for (int q = 0; q < 2; q++) {
            int idx = tid + q * 512;
            int j = idx >> 2, c = idx & 3;
            cpa16(smb + (uint32_t)(EPS_B + buf * 20480 + j * 80 + c * 16),
                  g_Wh + (size_t)j * 512 + k0 + c * 8);
        }
        CP_COMMIT();
    };

    const int a_row_in = (lane & 15);
    const int a_koff   = (lane >> 4) * 8;
    const int b_col_in = ((lane >> 4) & 1) * 8 + (lane & 7);
    const int b_koff   = ((lane >> 3) & 1) * 8;

    ldgA(0); stsA(0);
    issueB(0, 0);
    if (tid < 256) { sbu[tid] = bu[tid]; sWe[tid] = We[tid]; }

    for (int s = 0; s < 16; s++) {
        if (s + 1 < 16) { ldgA(s + 1); issueB((s + 1) & 1, s + 1); CP_WAIT1(); }
        else            { CP_WAIT0(); }
        __syncthreads();

        const uint32_t abase = smb + (s & 1) * 10240;
        const uint32_t bbase = smb + EPS_B + (s & 1) * 20480;

        #pragma unroll
        for (int kc = 0; kc < 2; kc++) {
            const int kw = kc * 16;
            uint32_t af[2][4];
            #pragma unroll
            for (int mi = 0; mi < 2; mi++) {
                ldsm_x4(af[mi][0], af[mi][1], af[mi][2], af[mi][3],
                        abase + (uint32_t)((wm * 32 + mi * 16 + a_row_in) * 80
                                           + (kw + a_koff) * 2));
            }
            uint32_t bf[8][2];
            #pragma unroll
            for (int n2 = 0; n2 < 4; n2++) {
                ldsm_x4(bf[n2 * 2][0], bf[n2 * 2][1], bf[n2 * 2 + 1][0], bf[n2 * 2 + 1][1],
                        bbase + (uint32_t)((wn * 64 + n2 * 16 + b_col_in) * 80
                                           + (kw + b_koff) * 2));
            }
            #pragma unroll
            for (int mi = 0; mi < 2; mi++)
                #pragma unroll
                for (int ni = 0; ni < 8; ni++)
                    mma_f16(acc[mi][ni][0], acc[mi][ni][1], acc[mi][ni][2], acc[mi][ni][3],
                            af[mi][0], af[mi][1], af[mi][2], af[mi][3],
                            bf[ni][0], bf[ni][1]);
        }
        if (s + 1 < 16) stsA((s + 1) & 1);
    }

    // Epilogue: sigmoid(h+bu)·We, row partials across wn
    float part[4] = {0.f, 0.f, 0.f, 0.f};
    #pragma unroll
    for (int mi = 0; mi < 2; mi++) {
        #pragma unroll
        for (int ni = 0; ni < 8; ni++) {
            const int c0 = wn * 64 + ni * 8 + t4 * 2;
            const int c1 = c0 + 1;
            const float w0 = sWe[c0], w1 = sWe[c1];
            const float b0 = sbu[c0], b1 = sbu[c1];
            float x;
            x = acc[mi][ni][0] + b0; part[mi * 2 + 0] += w0 / (1.f + __expf(-x));
            x = acc[mi][ni][1] + b1; part[mi * 2 + 0] += w1 / (1.f + __expf(-x));
            x = acc[mi][ni][2] + b0; part[mi * 2 + 1] += w0 / (1.f + __expf(-x));
            x = acc[mi][ni][3] + b1; part[mi * 2 + 1] += w1 / (1.f + __expf(-x));
        }
    }
    #pragma unroll
    for (int o = 1; o <= 2; o <<= 1)
        #pragma unroll
        for (int p = 0; p < 4; p++)
            part[p] += __shfl_xor_sync(0xffffffffu, part[p], o);
    if (t4 == 0) {
        #pragma unroll
        for (int p = 0; p < 4; p++) {
            int rl = wm * 32 + (p >> 1) * 16 + (p & 1) * 8 + g;
            ered[rl * 4 + wn] = part[p];
        }
    }
    __syncthreads();
    if (tid < 128) {
        int row = row0 + tid;
        if (row < n)
            g_e[row] = ered[tid * 4 + 0] + ered[tid * 4 + 1] + ered[tid * 4 + 2] + ered[tid * 4 + 3];
    }
}

// ---------------------------------------------------------------------------
// Segment softmax + pooling: float4 columns, 4 rows/group, 4x unrolled (MLP 4).
// ---------------------------------------------------------------------------
__global__ __launch_bounds__(256) void pool_kernel(const float* __restrict__ feats, int b) {
    __shared__ float red[256];
    __shared__ float sex[256];
    __shared__ float red4[4 * 256];
    const int seg = blockIdx.x;
    const int tid = threadIdx.x;
    const int base = g_off[seg];
    const int len  = g_off[seg + 1] - base;

    if (len <= 0) { g_rst[(size_t)seg * H + tid] = 0.f; return; }

    float m = -1e30f;
    for (int i = tid; i < len; i += 256) m = fmaxf(m, g_e[base + i]);
    red[tid] = m;
    __syncthreads();
    for (int o = 128; o > 0; o >>= 1) {
        if (tid < o) red[tid] = fmaxf(red[tid], red[tid + o]);
        __syncthreads();
    }
    m = red[0];
    __syncthreads();

    float d = 0.f;
    for (int i = tid; i < len; i += 256) d += __expf(g_e[base + i] - m);
    red[tid] = d;
    __syncthreads();
    for (int o = 128; o > 0; o >>= 1) {
        if (tid < o) red[tid] += red[tid + o];
        __syncthreads();
    }
    const float inv = 1.f / red[0];
    __syncthreads();

    // thread: row-group r4 (0..3), column quad cq (0..63)
    const int r4 = tid >> 6;
    const int cq = tid & 63;
    const float* fcol = feats + cq * 4;
    float4 acc = make_float4(0.f, 0.f, 0.f, 0.f);
    for (int s = 0; s < len; s += 256) {
        int c = len - s; if (c > 256) c = 256;
        sex[tid] = (tid < c) ? __expf(g_e[base + s + tid] - m) : 0.f;
        __syncthreads();
        int i = r4;
        // 4x unrolled: 4 independent float4 LDGs in flight per thread
        for (; i + 12 < c; i += 16) {
            const size_t r = (size_t)(base + s + i) * H;
            float4 v0 = *(const float4*)(fcol + r);
            float4 v1 = *(const float4*)(fcol + r + 4 * H);
            float4 v2 = *(const float4*)(fcol + r + 8 * H);
            float4 v3 = *(const float4*)(fcol + r + 12 * H);
            float w0 = sex[i], w1 = sex[i + 4], w2 = sex[i + 8], w3 = sex[i + 12];
            acc.x += w0 * v0.x; acc.y += w0 * v0.y; acc.z += w0 * v0.z; acc.w += w0 * v0.w;
            acc.x += w1 * v1.x; acc.y += w1 * v1.y; acc.z += w1 * v1.z; acc.w += w1 * v1.w;
            acc.x += w2 * v2.x; acc.y += w2 * v2.y; acc.z += w2 * v2.z; acc.w += w2 * v2.w;
            acc.x += w3 * v3.x; acc.y += w3 * v3.y; acc.z += w3 * v3.z; acc.w += w3 * v3.w;
        }
        for (; i < c; i += 4) {
            float w = sex[i];
            float4 v = *(const float4*)(fcol + (size_t)(base + s + i) * H);
            acc.x += w * v.x; acc.y += w * v.y; acc.z += w * v.z; acc.w += w * v.w;
        }
        __syncthreads();
    }
    *(float4*)(red4 + r4 * 256 + cq * 4) = acc;
    __syncthreads();
    float val = red4[tid] + red4[256 + tid] + red4[512 + tid] + red4[768 + tid];
    g_rst[(size_t)seg * H + tid] = val * inv;
}

// ---------------------------------------------------------------------------
// out = rst @ Wout.T, tf32 SIMT MMA with cp.async (known good, 17us).
// ---------------------------------------------------------------------------
#define PITCH 36
#define B_ST  (256 * PITCH)
#define A_ST_O (32 * PITCH)

__global__ __launch_bounds__(256, 2) void out_gemm_mma(
    float* __restrict__ out, const float* __restrict__ Wout, int m)
{
    extern __shared__ float sm[];
    float* As  = sm;
    float* Bsm = sm + 2 * A_ST_O;

    const int tid  = threadIdx.x;
    const int lane = tid & 31;
    const int warp = tid >> 5;
    const int wm = warp >> 2;
    const int wn = warp & 3;
    const int g  = lane >> 2;
    const int t4 = lane & 3;
    const int row0 = blockIdx.x * 32;

    const uint32_t sAb = (uint32_t)__cvta_generic_to_shared(As);
    const uint32_t sBb = (uint32_t)__cvta_generic_to_shared(Bsm);

    float acc[8][4];
    #pragma unroll
    for (int ni = 0; ni < 8; ni++)
        #pragma unroll
        for (int q = 0; q < 4; q++) acc[ni][q] = 0.f;

    auto issue = [&](int buf, int k0) {
        {
            int ar = tid >> 3, kq = tid & 7;
            int grow = row0 + ar; if (grow >= m) grow = m - 1;
            cpa16(sAb + (uint32_t)(buf * A_ST_O + ar * PITCH + kq * 4) * 4u,
                  g_rst + (size_t)grow * H + k0 + kq * 4);
        }
        #pragma unroll
        for (int q = 0; q < 8; q++) {
            cpa16(sBb + (uint32_t)(buf * B_ST + tid * PITCH + q * 4) * 4u,
                  Wout + (size_t)tid * H + k0 + q * 4);
        }
        CP_COMMIT();
    };

    issue(0, 0);
    for (int s = 0; s < 8; s++) {
        if (s + 1 < 8) { issue((s + 1) & 1, (s + 1) * 32); CP_WAIT1(); }
        else           { CP_WAIT0(); }
        __syncthreads();

        const float* Ab = As  + (s & 1) * A_ST_O;
        const float* Bb = Bsm + (s & 1) * B_ST;

        #pragma unroll
        for (int ks = 0; ks < 4; ks++) {
            const int kb = ks * 8;
            const float* ab = Ab + (wm * 16) * PITCH;
            uint32_t a0 = __float_as_uint(ab[(g    ) * PITCH + kb + t4    ]);
            uint32_t a1 = __float_as_uint(ab[(g + 8) * PITCH + kb + t4    ]);
            uint32_t a2 = __float_as_uint(ab[(g    ) * PITCH + kb + t4 + 4]);
            uint32_t a3 = __float_as_uint(ab[(g + 8) * PITCH + kb + t4 + 4]);
            #pragma unroll
            for (int ni = 0; ni < 8; ni++) {
                const int nc = wn * 64 + ni * 8 + g;
                uint32_t b0 = __float_as_uint(Bb[nc * PITCH + kb + t4    ]);
                uint32_t b1 = __float_as_uint(Bb[nc * PITCH + kb + t4 + 4]);
                mma_tf32(acc[ni][0], acc[ni][1], acc[ni][2], acc[ni][3],
                         a0, a1, a2, a3, b0, b1);
            }
        }
        __syncthreads();
    }

    const int r0 = row0 + wm * 16 + g;
    const int r1 = r0 + 8;
    #pragma unroll
    for (int ni = 0; ni < 8; ni++) {
        const int c0 = wn * 64 + ni * 8 + t4 * 2;
        if (r0 < m) *(float2*)(out + (size_t)r0 * H + c0) = make_float2(acc[ni][0], acc[ni][1]);
        if (r1 < m) *(float2*)(out + (size_t)r1 * H + c0) = make_float2(acc[ni][2], acc[ni][3]);
    }
}

extern "C" void kernel_launch(void* const* d_in, const int* in_sizes, int n_in,
                              void* d_out, int out_size) {
    const float* feats = (const float*)d_in[0];
    const float* ctx   = (const float*)d_in[1];
    const void*  lens  = d_in[2];
    const float* Wu    = (const float*)d_in[3];
    const float* bu    = (const float*)d_in[4];
    const float* Wv    = (const float*)d_in[5];
    const float* We    = (const float*)d_in[6];
    const float* Wout  = (const float*)d_in[7];
    float* out = (float*)d_out;

    const int n = in_sizes[0] / H;
    const int b = out_size / H;

    const int smem_out = (2 * A_ST_O + 2 * B_ST) * 4;
    cudaFuncSetAttribute(e_gemm_f16,   cudaFuncAttributeMaxDynamicSharedMemorySize, EPS_TOT);
    cudaFuncSetAttribute(out_gemm_mma, cudaFuncAttributeMaxDynamicSharedMemorySize, smem_out);

    float* Wout_r = nullptr; cudaGetSymbolAddress((void**)&Wout_r, g_Wr);

    scan_kernel<<<1, 1024>>>(lens, b, n);
    conv_w_kernel<<<256, 256>>>(Wu, Wv, Wout);
    e_gemm_f16<<<(n + 127) / 128, 512, EPS_TOT>>>(feats, ctx, bu, We, n);
    pool_kernel<<<b, 256>>>(feats, b);
    out_gemm_mma<<<(b + 31) / 32, 256, smem_out>>>(out, Wout_r, b);
}

// round 11
// speedup vs baseline: 13.4899x; 1.3356x over previous
#include <cuda_runtime.h>
#include <cuda_fp16.h>
#include <cstdint>
#include <cstring>

#define H 256
#define NMAX 204800
#define BMAX 4096

__device__ float  g_e[NMAX];           // e scores, then alpha (in-place)
__device__ int    g_seg[NMAX];         // segment id per row
__device__ float  g_rst[BMAX * H];
__device__ int    g_off[BMAX + 1];
__device__ __half g_Wh[256 * 512];     // [col j][Wu row j | Wv row j]
__device__ float  g_Wr[H * H];         // tf32-RNA rounded Wout

// ---------------------------------------------------------------------------
// helpers
// ---------------------------------------------------------------------------
__device__ __forceinline__ uint32_t h2u(__half2 h) {
    uint32_t u;
    memcpy(&u, &h, 4);
    return u;
}
__device__ __forceinline__ void cpa16(uint32_t dst, const void* src) {
    asm volatile("cp.async.cg.shared.global [%0], [%1], 16;\n" :: "r"(dst), "l"(src));
}
#define CP_COMMIT() asm volatile("cp.async.commit_group;\n" ::: "memory")
#define CP_WAIT0()  asm volatile("cp.async.wait_group 0;\n" ::: "memory")
#define CP_WAIT1()  asm volatile("cp.async.wait_group 1;\n" ::: "memory")

__device__ __forceinline__ void mma_f16(float& d0, float& d1, float& d2, float& d3,
                                        uint32_t a0, uint32_t a1, uint32_t a2, uint32_t a3,
                                        uint32_t b0, uint32_t b1) {
    asm volatile("mma.sync.aligned.m16n8k16.row.col.f32.f16.f16.f32 "
                 "{%0,%1,%2,%3},{%4,%5,%6,%7},{%8,%9},{%0,%1,%2,%3};\n"
                 : "+f"(d0), "+f"(d1), "+f"(d2), "+f"(d3)
                 : "r"(a0), "r"(a1), "r"(a2), "r"(a3), "r"(b0), "r"(b1));
}
__device__ __forceinline__ void mma_tf32(float& d0, float& d1, float& d2, float& d3,
                                         uint32_t a0, uint32_t a1, uint32_t a2, uint32_t a3,
                                         uint32_t b0, uint32_t b1) {
    asm volatile("mma.sync.aligned.m16n8k8.row.col.f32.tf32.tf32.f32 "
                 "{%0,%1,%2,%3},{%4,%5,%6,%7},{%8,%9},{%0,%1,%2,%3};\n"
                 : "+f"(d0), "+f"(d1), "+f"(d2), "+f"(d3)
                 : "r"(a0), "r"(a1), "r"(a2), "r"(a3), "r"(b0), "r"(b1));
}
__device__ __forceinline__ void ldsm_x4(uint32_t& r0, uint32_t& r1, uint32_t& r2, uint32_t& r3,
                                        uint32_t addr) {
    asm volatile("ldmatrix.sync.aligned.m8n8.x4.shared.b16 {%0,%1,%2,%3}, [%4];"
                 : "=r"(r0), "=r"(r1), "=r"(r2), "=r"(r3) : "r"(addr));
}

// ---------------------------------------------------------------------------
// Prefix scan of ragged lengths (runtime int32/int64 detection).
// ---------------------------------------------------------------------------
__global__ __launch_bounds__(1024) void scan_kernel(const void* lens_raw, int b, int n_total) {
    __shared__ long long s[1024];
    __shared__ int use64;
    const int tid = threadIdx.x;
    const int* p32 = (const int*)lens_raw;

    long long local = 0;
    for (int i = tid; i < b; i += 1024) local += (long long)p32[i];
    s[tid] = local;
    __syncthreads();
    for (int o = 512; o > 0; o >>= 1) {
        if (tid < o) s[tid] += s[tid + o];
        __syncthreads();
    }
    if (tid == 0) use64 = (s[0] == (long long)n_total) ? 0 : 1;
    __syncthreads();
    const int u64 = use64;
    __syncthreads();

    const int PER = 4;
    long long v[PER];
    long long loc = 0;
    #pragma unroll
    for (int q = 0; q < PER; q++) {
        int i = tid * PER + q;
        long long val = 0;
        if (i < b) val = u64 ? ((const long long*)lens_raw)[i] : (long long)p32[i];
        v[q] = val;
        loc += val;
    }
    s[tid] = loc;
    __syncthreads();
    for (int o = 1; o < 1024; o <<= 1) {
        long long t = (tid >= o) ? s[tid - o] : 0;
        __syncthreads();
        s[tid] += t;
        __syncthreads();
    }
    long long run = s[tid] - loc;
    #pragma unroll
    for (int q = 0; q < PER; q++) {
        int i = tid * PER + q;
        if (i < b) {
            g_off[i] = (int)run;
            run += v[q];
            if (i == b - 1) g_off[b] = (int)run;
        }
    }
}

// ---------------------------------------------------------------------------
// Weight prep: fp16 [Wu|Wv] K-major per output col; tf32-RNA Wout.
// ---------------------------------------------------------------------------
__global__ __launch_bounds__(256) void conv_w_kernel(
    const float* __restrict__ Wu, const float* __restrict__ Wv, const float* __restrict__ Wout)
{
    const int j = blockIdx.x, k = threadIdx.x;
    g_Wh[j * 512 + k]       = __float2half_rn(Wu[j * H + k]);
    g_Wh[j * 512 + 256 + k] = __float2half_rn(Wv[j * H + k]);
    uint32_t c;
    asm("cvt.rna.tf32.f32 %0, %1;" : "=r"(c) : "f"(Wout[j * H + k]));
    g_Wr[j * H + k] = __uint_as_float(c);
}

// ---------------------------------------------------------------------------
// Fused e-GEMM, fp16 m16n8k16, LDSM fragments, fp32 A loaded+converted inline.
// ---------------------------------------------------------------------------
#define EPS_B   20480
#define EPS_BU  61440
#define EPS_WE  62464
#define EPS_ER  63488
#define EPS_TOT 65536

__global__ __launch_bounds__(512, 1) void e_gemm_f16(
    const float* __restrict__ feats, const float* __restrict__ ctx,
    const float* __restrict__ bu, const float* __restrict__ We, int n)
{
    extern __shared__ char smc[];
    const uint32_t smb = (uint32_t)__cvta_generic_to_shared(smc);
    float* sbu  = (float*)(smc + EPS_BU);
    float* sWe  = (float*)(smc + EPS_WE);
    float* ered = (float*)(smc + EPS_ER);   // [128][4]

    const int tid  = threadIdx.x;
    const int lane = tid & 31;
    const int warp = tid >> 5;
    const int wm = warp >> 2;
    const int wn = warp & 3;
    const int g  = lane >> 2;
    const int t4 = lane & 3;
    const int row0 = blockIdx.x * 128;

    const int ar = tid >> 2;
    const int ac = tid & 3;
    int arow = row0 + ar; if (arow >= n) arow = n - 1;

    float acc[2][8][4];
    #pragma unroll
    for (int mi = 0; mi < 2; mi++)
        #pragma unroll
        for (int ni = 0; ni < 8; ni++)
            #pragma unroll
            for (int q = 0; q < 4; q++) acc[mi][ni][q] = 0.f;

    float4 avA, avB;

    auto ldgA = [&](int sidx) {
        const int k0 = sidx * 32;
        const float* Ap = (k0 < 256) ? feats : ctx;
        const float* p = Ap + (size_t)arow * H + (k0 & 255) + ac * 8;
        avA = *(const float4*)p;
        avB = *(const float4*)(p + 4);
    };
    auto stsA = [&](int buf) {
        uint4 u;
        u.x = h2u(__floats2half2_rn(avA.x, avA.y));
        u.y = h2u(__floats2half2_rn(avA.z, avA.w));
        u.z = h2u(__floats2half2_rn(avB.x, avB.y));
        u.w = h2u(__floats2half2_rn(avB.z, avB.w));
        *(uint4*)(smc + buf * 10240 + ar * 80 + ac * 16) = u;
    };
    auto issueB = [&](int buf, int sidx) {
        const int k0 = sidx * 32;
        #pragma unroll
        for (int q = 0; q < 2; q++) {
            int idx = tid + q * 512;
            int j = idx >> 2, c = idx & 3;
            cpa16(smb + (uint32_t)(EPS_B + buf * 20480 + j * 80 + c * 16),
                  g_Wh + (size_t)j * 512 + k0 + c * 8);
        }
        CP_COMMIT();
    };

    const int a_row_in = (lane & 15);
    const int a_koff   = (lane >> 4) * 8;
    const int b_col_in = ((lane >> 4) & 1) * 8 + (lane & 7);
    const int b_koff   = ((lane >> 3) & 1) * 8;

    ldgA(0); stsA(0);
    issueB(0, 0);
    if (tid < 256) { sbu[tid] = bu[tid]; sWe[tid] = We[tid]; }

    for (int s = 0; s < 16; s++) {
        if (s + 1 < 16) { ldgA(s + 1); issueB((s + 1) & 1, s + 1); CP_WAIT1(); }
        else            { CP_WAIT0(); }
        __syncthreads();

        const uint32_t abase = smb + (s & 1) * 10240;
        const uint32_t bbase = smb + EPS_B + (s & 1) * 20480;

        #pragma unroll
        for (int kc = 0; kc < 2; kc++) {
            const int kw = kc * 16;
            uint32_t af[2][4];
            #pragma unroll
            for (int mi = 0; mi < 2; mi++) {
                ldsm_x4(af[mi][0], af[mi][1], af[mi][2], af[mi][3],
                        abase + (uint32_t)((wm * 32 + mi * 16 + a_row_in) * 80
                                           + (kw + a_koff) * 2));
            }
            uint32_t bf[8][2];
            #pragma unroll
            for (int n2 = 0; n2 < 4; n2++) {
                ldsm_x4(bf[n2 * 2][0], bf[n2 * 2][1], bf[n2 * 2 + 1][0], bf[n2 * 2 + 1][1],
                        bbase + (uint32_t)((wn * 64 + n2 * 16 + b_col_in) * 80
                                           + (kw + b_koff) * 2));
            }
            #pragma unroll
            for (int mi = 0; mi < 2; mi++)
                #pragma unroll
                for (int ni = 0; ni < 8; ni++)
                    mma_f16(acc[mi][ni][0], acc[mi][ni][1], acc[mi][ni][2], acc[mi][ni][3],
                            af[mi][0], af[mi][1], af[mi][2], af[mi][3],
                            bf[ni][0], bf[ni][1]);
        }
        if (s + 1 < 16) stsA((s + 1) & 1);
    }

    // Epilogue: sigmoid(h+bu)·We, row partials across wn
    float part[4] = {0.f, 0.f, 0.f, 0.f};
    #pragma unroll
    for (int mi = 0; mi < 2; mi++) {
        #pragma unroll
        for (int ni = 0; ni < 8; ni++) {
            const int c0 = wn * 64 + ni * 8 + t4 * 2;
            const int c1 = c0 + 1;
            const float w0 = sWe[c0], w1 = sWe[c1];
            const float b0 = sbu[c0], b1 = sbu[c1];
            float x;
            x = acc[mi][ni][0] + b0; part[mi * 2 + 0] += w0 / (1.f + __expf(-x));
            x = acc[mi][ni][1] + b1; part[mi * 2 + 0] += w1 / (1.f + __expf(-x));
            x = acc[mi][ni][2] + b0; part[mi * 2 + 1] += w0 / (1.f + __expf(-x));
            x = acc[mi][ni][3] + b1; part[mi * 2 + 1] += w1 / (1.f + __expf(-x));
        }
    }
    #pragma unroll
    for (int o = 1; o <= 2; o <<= 1)
        #pragma unroll
        for (int p = 0; p < 4; p++)
            part[p] += __shfl_xor_sync(0xffffffffu, part[p], o);
    if (t4 == 0) {
        #pragma unroll
        for (int p = 0; p < 4; p++) {
            int rl = wm * 32 + (p >> 1) * 16 + (p & 1) * 8 + g;
            ered[rl * 4 + wn] = part[p];
        }
    }
    __syncthreads();
    if (tid < 128) {
        int row = row0 + tid;
        if (row < n)
            g_e[row] = ered[tid * 4 + 0] + ered[tid * 4 + 1] + ered[tid * 4 + 2] + ered[tid * 4 + 3];
    }
}

// ---------------------------------------------------------------------------
// Zero g_rst (atomic accumulation target).
// ---------------------------------------------------------------------------
__global__ __launch_bounds__(1024) void zero_rst_kernel(int total4) {
    int i = blockIdx.x * 1024 + threadIdx.x;
    if (i < total4) ((float4*)g_rst)[i] = make_float4(0.f, 0.f, 0.f, 0.f);
}

// ---------------------------------------------------------------------------
// One WARP per segment: softmax over g_e in place (alpha), write seg ids.
// No __syncthreads anywhere.
// ---------------------------------------------------------------------------
__global__ __launch_bounds__(256) void alpha_kernel(int b) {
    const int seg = blockIdx.x * 8 + (threadIdx.x >> 5);
    if (seg >= b) return;
    const int lane = threadIdx.x & 31;
    const int base = g_off[seg];
    const int len  = g_off[seg + 1] - base;
    if (len <= 0) return;

    float m = -1e30f;
    for (int i = lane; i < len; i += 32) m = fmaxf(m, g_e[base + i]);
    #pragma unroll
    for (int o = 16; o > 0; o >>= 1) m = fmaxf(m, __shfl_xor_sync(0xffffffffu, m, o));

    float d = 0.f;
    for (int i = lane; i < len; i += 32) d += __expf(g_e[base + i] - m);
    #pragma unroll
    for (int o = 16; o > 0; o >>= 1) d += __shfl_xor_sync(0xffffffffu, d, o);
    const float inv = 1.f / d;

    for (int i = lane; i < len; i += 32) {
        g_e[base + i] = __expf(g_e[base + i] - m) * inv;
        g_seg[base + i] = seg;
    }
}

// ---------------------------------------------------------------------------
// Flat weighted pooling: 64 global rows per block, streaming, atomic flush
// at segment boundaries. thread = (row-group r4, column quad cq).
// ---------------------------------------------------------------------------
__global__ __launch_bounds__(256) void pool_flat_kernel(const float* __restrict__ feats, int n) {
    const int tid = threadIdx.x;
    const int r4 = tid >> 6;        // 0..3
    const int cq = tid & 63;        // 0..63
    const int row0 = blockIdx.x * 64 + r4;
    if (row0 >= n) return;
    const float* fcol = feats + cq * 4;

    int cur = g_seg[row0];
    float4 acc = make_float4(0.f, 0.f, 0.f, 0.f);

    #pragma unroll
    for (int j0 = 0; j0 < 16; j0 += 4) {
        float4 v[4]; float a[4]; int sg[4];
        #pragma unroll
        for (int k = 0; k < 4; k++) {
            int row = row0 + (j0 + k) * 4;
            bool ok = row < n;
            int rr = ok ? row : n - 1;
            v[k] = *(const float4*)(fcol + (size_t)rr * H);
            a[k] = ok ? g_e[rr] : 0.f;
            sg[k] = g_seg[rr];
        }
        #pragma unroll
        for (int k = 0; k < 4; k++) {
            if (sg[k] != cur) {
                float* dst = g_rst + (size_t)cur * H + cq * 4;
                atomicAdd(dst + 0, acc.x);
                atomicAdd(dst + 1, acc.y);
                atomicAdd(dst + 2, acc.z);
                atomicAdd(dst + 3, acc.w);
                acc = make_float4(0.f, 0.f, 0.f, 0.f);
                cur = sg[k];
            }
            acc.x += a[k] * v[k].x;
            acc.y += a[k] * v[k].y;
            acc.z += a[k] * v[k].z;
            acc.w += a[k] * v[k].w;
        }
    }
    float* dst = g_rst + (size_t)cur * H + cq * 4;
    atomicAdd(dst + 0, acc.x);
    atomicAdd(dst + 1, acc.y);
    atomicAdd(dst + 2, acc.z);
    atomicAdd(dst + 3, acc.w);
}

// ---------------------------------------------------------------------------
// out = rst @ Wout.T, tf32 SIMT MMA with cp.async (known good, 17us).
// ---------------------------------------------------------------------------
#define PITCH 36
#define B_ST  (256 * PITCH)
#define A_ST_O (32 * PITCH)

__global__ __launch_bounds__(256, 2) void out_gemm_mma(
    float* __restrict__ out, const float* __restrict__ Wout, int m)
{
    extern __shared__ float sm[];
    float* As  = sm;
    float* Bsm = sm + 2 * A_ST_O;

    const int tid  = threadIdx.x;
    const int lane = tid & 31;
    const int warp = tid >> 5;
    const int wm = warp >> 2;
    const int wn = warp & 3;
    const int g  = lane >> 2;
    const int t4 = lane & 3;
    const int row0 = blockIdx.x * 32;

    const uint32_t sAb = (uint32_t)__cvta_generic_to_shared(As);
    const uint32_t sBb = (uint32_t)__cvta_generic_to_shared(Bsm);

    float acc[8][4];
    #pragma unroll
    for (int ni = 0; ni < 8; ni++)
        #pragma unroll
        for (int q = 0; q < 4; q++) acc[ni][q] = 0.f;

    auto issue = [&](int buf, int k0) {
        {
            int ar = tid >> 3, kq = tid & 7;
            int grow = row0 + ar; if (grow >= m) grow = m - 1;
            cpa16(sAb + (uint32_t)(buf * A_ST_O + ar * PITCH + kq * 4) * 4u,
                  g_rst + (size_t)grow * H + k0 + kq * 4);
        }
        #pragma unroll
        for (int q = 0; q < 8; q++) {
            cpa16(sBb + (uint32_t)(buf * B_ST + tid * PITCH + q * 4) * 4u,
                  Wout + (size_t)tid * H + k0 + q * 4);
        }
        CP_COMMIT();
    };

    issue(0, 0);
    for (int s = 0; s < 8; s++) {
        if (s + 1 < 8) { issue((s + 1) & 1, (s + 1) * 32); CP_WAIT1(); }
        else           { CP_WAIT0(); }
        __syncthreads();

        const float* Ab = As  + (s & 1) * A_ST_O;
        const float* Bb = Bsm + (s & 1) * B_ST;

        #pragma unroll
        for (int ks = 0; ks < 4; ks++) {
            const int kb = ks * 8;
            const float* ab = Ab + (wm * 16) * PITCH;
            uint32_t a0 = __float_as_uint(ab[(g    ) * PITCH + kb + t4    ]);
            uint32_t a1 = __float_as_uint(ab[(g + 8) * PITCH + kb + t4    ]);
            uint32_t a2 = __float_as_uint(ab[(g    ) * PITCH + kb + t4 + 4]);
            uint32_t a3 = __float_as_uint(ab[(g + 8) * PITCH + kb + t4 + 4]);
            #pragma unroll
            for (int ni = 0; ni < 8; ni++) {
                const int nc = wn * 64 + ni * 8 + g;
                uint32_t b0 = __float_as_uint(Bb[nc * PITCH + kb + t4    ]);
                uint32_t b1 = __float_as_uint(Bb[nc * PITCH + kb + t4 + 4]);
                mma_tf32(acc[ni][0], acc[ni][1], acc[ni][2], acc[ni][3],
                         a0, a1, a2, a3, b0, b1);
            }
        }
        __syncthreads();
    }

    const int r0 = row0 + wm * 16 + g;
    const int r1 = r0 + 8;
    #pragma unroll
    for (int ni = 0; ni < 8; ni++) {
        const int c0 = wn * 64 + ni * 8 + t4 * 2;
        if (r0 < m) *(float2*)(out + (size_t)r0 * H + c0) = make_float2(acc[ni][0], acc[ni][1]);
        if (r1 < m) *(float2*)(out + (size_t)r1 * H + c0) = make_float2(acc[ni][2], acc[ni][3]);
    }
}

extern "C" void kernel_launch(void* const* d_in, const int* in_sizes, int n_in,
                              void* d_out, int out_size) {
    const float* feats = (const float*)d_in[0];
    const float* ctx   = (const float*)d_in[1];
    const void*  lens  = d_in[2];
    const float* Wu    = (const float*)d_in[3];
    const float* bu    = (const float*)d_in[4];
    const float* Wv    = (const float*)d_in[5];
    const float* We    = (const float*)d_in[6];
    const float* Wout  = (const float*)d_in[7];
    float* out = (float*)d_out;

    const int n = in_sizes[0] / H;
    const int b = out_size / H;

    const int smem_out = (2 * A_ST_O + 2 * B_ST) * 4;
    cudaFuncSetAttribute(e_gemm_f16,   cudaFuncAttributeMaxDynamicSharedMemorySize, EPS_TOT);
    cudaFuncSetAttribute(out_gemm_mma, cudaFuncAttributeMaxDynamicSharedMemorySize, smem_out);

    float* Wout_r = nullptr; cudaGetSymbolAddress((void**)&Wout_r, g_Wr);

    const int total4 = b * H / 4;
    scan_kernel<<<1, 1024>>>(lens, b, n);
    conv_w_kernel<<<256, 256>>>(Wu, Wv, Wout);
    zero_rst_kernel<<<(total4 + 1023) / 1024, 1024>>>(total4);
    e_gemm_f16<<<(n + 127) / 128, 512, EPS_TOT>>>(feats, ctx, bu, We, n);
    alpha_kernel<<<(b + 7) / 8, 256>>>(b);
    pool_flat_kernel<<<(n + 63) / 64, 256>>>(feats, n);
    out_gemm_mma<<<(b + 31) / 32, 256, smem_out>>>(out, Wout_r, b);
}